// round 12
// baseline (speedup 1.0000x reference)
#include <cuda_runtime.h>
#include <cuda_bf16.h>
#include <cstdint>

#define NU 50000
#define NI 50000
#define NE 800000
#define HD 128
#define NN (NI + NU)

typedef unsigned long long u64;

// ---------------- f32x2 packed-FMA helpers (Blackwell FFMA2) ----------------
__device__ __forceinline__ u64 pk2(float v) {
    u64 r; asm("mov.b64 %0, {%1,%1};" : "=l"(r) : "f"(v)); return r;
}
__device__ __forceinline__ void fma2(u64& d, u64 a, u64 b) {
    asm("fma.rn.f32x2 %0, %1, %2, %3;" : "=l"(d) : "l"(a), "l"(b), "l"(d));
}
__device__ __forceinline__ float2 up2(u64 v) {
    float2 f; asm("mov.b64 {%0,%1}, %2;" : "=f"(f.x), "=f"(f.y) : "l"(v)); return f;
}

// ---------------- device scratch ----------------
__device__ __align__(16) float g_hu [(size_t)NU * HD];
__device__ __align__(16) float g_hi [(size_t)NI * HD];
__device__ __align__(16) float g_hu2[(size_t)NU * HD];
__device__ __align__(16) float g_hi2[(size_t)NI * HD];
__device__ __align__(16) float g_hu3[(size_t)NU * HD];

__device__ __align__(16) int g_deg[NN];         // [deg_item | deg_user]
__device__ __align__(16) int g_rowptr[NN + 1];  // combined CSR rowptr
__device__ __align__(16) int g_fill[NN];        // fill cursors
__device__ __align__(16) int g_bsums[128];      // block sums for 2-level scan
__device__ __align__(16) int g_esrc[2 * NE];    // combined grouped edge sources

// ---------------- zero ----------------
__global__ void zero_kernel(float4* __restrict__ p, int n4) {
    int i = blockIdx.x * blockDim.x + threadIdx.x;
    if (i < n4) p[i] = make_float4(0.f, 0.f, 0.f, 0.f);
}

// ---------------- CSR: histogram over both relations (2 edges/thread) ----------------
__global__ void hist2_kernel(const int* __restrict__ ei_a, const int* __restrict__ ei_b,
                             int* __restrict__ deg)
{
    int t = blockIdx.x * blockDim.x + threadIdx.x;
    if (t < NE / 2) {
        int2 d = *reinterpret_cast<const int2*>(ei_a + NE + 2 * t);
        atomicAdd(&deg[d.x], 1);
        atomicAdd(&deg[d.y], 1);
    } else if (t < NE) {
        int2 d = *reinterpret_cast<const int2*>(ei_b + NE + 2 * (t - NE / 2));
        atomicAdd(&deg[NI + d.x], 1);
        atomicAdd(&deg[NI + d.y], 1);
    }
}

// ---------------- CSR: two-level scan ----------------
__global__ void __launch_bounds__(1024) scan1_kernel(
    const int* __restrict__ deg, int* __restrict__ rowptr, int* __restrict__ bsums, int n)
{
    __shared__ int ws[32];
    const int tid = threadIdx.x, lane = tid & 31, wid = tid >> 5;
    int i = blockIdx.x * 1024 + tid;
    int v = (i < n) ? deg[i] : 0;
    int x = v;
#pragma unroll
    for (int off = 1; off < 32; off <<= 1) {
        int y = __shfl_up_sync(0xffffffffu, x, off);
        if (lane >= off) x += y;
    }
    if (lane == 31) ws[wid] = x;
    __syncthreads();
    if (tid < 32) {
        int s = ws[tid];
#pragma unroll
        for (int off = 1; off < 32; off <<= 1) {
            int y = __shfl_up_sync(0xffffffffu, s, off);
            if (tid >= off) s += y;
        }
        ws[tid] = s;
    }
    __syncthreads();
    int prev = wid ? ws[wid - 1] : 0;
    if (i < n) rowptr[i] = prev + x - v;
    if (tid == 1023) bsums[blockIdx.x] = prev + x;
}

__global__ void __launch_bounds__(1024) scan2_kernel(int* __restrict__ data, int n) {
    __shared__ int ws[32];
    const int tid = threadIdx.x, lane = tid & 31, wid = tid >> 5;
    int v = (tid < n) ? data[tid] : 0;
    int x = v;
#pragma unroll
    for (int off = 1; off < 32; off <<= 1) {
        int y = __shfl_up_sync(0xffffffffu, x, off);
        if (lane >= off) x += y;
    }
    if (lane == 31) ws[wid] = x;
    __syncthreads();
    if (tid < 32) {
        int s = ws[tid];
#pragma unroll
        for (int off = 1; off < 32; off <<= 1) {
            int y = __shfl_up_sync(0xffffffffu, s, off);
            if (tid >= off) s += y;
        }
        ws[tid] = s;
    }
    __syncthreads();
    int prev = wid ? ws[wid - 1] : 0;
    if (tid < n) data[tid] = prev + x - v;
}

__global__ void scan3_kernel(int* __restrict__ rowptr, int* __restrict__ fill,
                             const int* __restrict__ bsums, int n, int total)
{
    int i = blockIdx.x * blockDim.x + threadIdx.x;
    if (i < n) {
        int v = rowptr[i] + bsums[i >> 10];
        rowptr[i] = v;
        fill[i] = v;
    }
    if (i == 0) rowptr[n] = total;
}

// ---------------- CSR: fill edge-source buckets (2 edges/thread) ----------------
__global__ void fill2_kernel(const int* __restrict__ ei_a, const int* __restrict__ ei_b,
                             int* __restrict__ cursor, int* __restrict__ esrc)
{
    int t = blockIdx.x * blockDim.x + threadIdx.x;
    if (t < NE / 2) {
        int e = 2 * t;
        int2 d = *reinterpret_cast<const int2*>(ei_a + NE + e);
        int2 s = *reinterpret_cast<const int2*>(ei_a + e);
        esrc[atomicAdd(&cursor[d.x], 1)] = s.x;
        esrc[atomicAdd(&cursor[d.y], 1)] = s.y;
    } else if (t < NE) {
        int e = 2 * (t - NE / 2);
        int2 d = *reinterpret_cast<const int2*>(ei_b + NE + e);
        int2 s = *reinterpret_cast<const int2*>(ei_b + e);
        esrc[atomicAdd(&cursor[NI + d.x], 1)] = s.x;
        esrc[atomicAdd(&cursor[NI + d.y], 1)] = s.y;
    }
}

// ---------------- fused SAGE layer: gather-mean + GEMM + norm + relu + residual ----
// h_out[r] = relu( L2norm( mean_{s in N(r)} src[s] @ Wl + bl + h_in[r] @ Wr ) ) + h_in[r]
// 64 dst rows/block, 128 threads, dynamic smem.
// Phase 1: warps gather neighbor means into Am[64][132] (padded stride vs bank conflicts).
// Phase 2: register-tiled FFMA2 GEMM identical to previous combine kernel.
#define AMS 132           // padded row stride (floats) for Am
__global__ void __launch_bounds__(128) sage_fused_kernel(
    const float* __restrict__ src_feat, const float* __restrict__ h_in,
    float* __restrict__ h_out,
    const int* __restrict__ rowptr, const int* __restrict__ esrc,
    const float* __restrict__ wl, const float* __restrict__ bl,
    const float* __restrict__ wr, int n)
{
    extern __shared__ __align__(16) float smem[];
    float* Am  = smem;                 // 64*132 = 8448
    float* Wls = Am + 64 * AMS;        // 2048
    float* Wrs = Wls + 2048;           // 2048
    float* As  = Wrs + 2048;           // 1024
    float* Xs  = As + 1024;            // 1024  -> total 14592 floats = 58368 B

    const int tid  = threadIdx.x;
    const int wid  = tid >> 5;
    const int lane = tid & 31;
    const int row0 = blockIdx.x * 64;

    // ---- phase 1: gather means for this block's 64 rows ----
    for (int r = wid; r < 64; r += 4) {
        int node = row0 + r;
        float4 acc = make_float4(0.f, 0.f, 0.f, 0.f);
        if (node < n) {
            int beg = __ldg(&rowptr[node]);
            int end = __ldg(&rowptr[node + 1]);
            int e = beg;
            for (; e + 4 <= end; e += 4) {
                int s0 = __ldg(&esrc[e]);
                int s1 = __ldg(&esrc[e + 1]);
                int s2 = __ldg(&esrc[e + 2]);
                int s3 = __ldg(&esrc[e + 3]);
                float4 v0 = reinterpret_cast<const float4*>(src_feat + (size_t)s0 * HD)[lane];
                float4 v1 = reinterpret_cast<const float4*>(src_feat + (size_t)s1 * HD)[lane];
                float4 v2 = reinterpret_cast<const float4*>(src_feat + (size_t)s2 * HD)[lane];
                float4 v3 = reinterpret_cast<const float4*>(src_feat + (size_t)s3 * HD)[lane];
                acc.x += (v0.x + v1.x) + (v2.x + v3.x);
                acc.y += (v0.y + v1.y) + (v2.y + v3.y);
                acc.z += (v0.z + v1.z) + (v2.z + v3.z);
                acc.w += (v0.w + v1.w) + (v2.w + v3.w);
            }
            for (; e < end; e++) {
                int s = __ldg(&esrc[e]);
                float4 v = reinterpret_cast<const float4*>(src_feat + (size_t)s * HD)[lane];
                acc.x += v.x; acc.y += v.y; acc.z += v.z; acc.w += v.w;
            }
            float inv = 1.0f / fmaxf((float)(end - beg), 1.0f);
            acc.x *= inv; acc.y *= inv; acc.z *= inv; acc.w *= inv;
        }
        *reinterpret_cast<float4*>(Am + r * AMS + lane * 4) = acc;
    }
    __syncthreads();

    // ---- phase 2: GEMM + epilogue ----
    const int tx = tid & 15;
    const int ty = tid >> 4;

    u64 acc[8][4];
#pragma unroll
    for (int i = 0; i < 8; i++)
#pragma unroll
        for (int j = 0; j < 4; j++) acc[i][j] = 0ull;

    const int lrow  = tid >> 1;
    const int lhalf = tid & 1;
    const int grow  = min(row0 + lrow, n - 1);

    for (int kc = 0; kc < 8; kc++) {
        const int k0 = kc * 16;
        {
            const float4* sl = reinterpret_cast<const float4*>(wl + k0 * 128);
            const float4* sr = reinterpret_cast<const float4*>(wr + k0 * 128);
            float4* dl = reinterpret_cast<float4*>(Wls);
            float4* dr = reinterpret_cast<float4*>(Wrs);
#pragma unroll
            for (int i = 0; i < 4; i++) {
                dl[tid + i * 128] = sl[tid + i * 128];
                dr[tid + i * 128] = sr[tid + i * 128];
            }
        }
        {
            // A from smem Am; X from global h_in
            const float* ap = Am + lrow * AMS + k0 + lhalf * 8;
            const float* xp = h_in + (size_t)grow * HD + k0 + lhalf * 8;
            float4 a0 = *reinterpret_cast<const float4*>(ap);
            float4 a1 = *reinterpret_cast<const float4*>(ap + 4);
            float4 x0 = *reinterpret_cast<const float4*>(xp);
            float4 x1 = *reinterpret_cast<const float4*>(xp + 4);
            int kb = lhalf * 8;
            As[(kb + 0) * 64 + lrow] = a0.x;
            As[(kb + 1) * 64 + lrow] = a0.y;
            As[(kb + 2) * 64 + lrow] = a0.z;
            As[(kb + 3) * 64 + lrow] = a0.w;
            As[(kb + 4) * 64 + lrow] = a1.x;
            As[(kb + 5) * 64 + lrow] = a1.y;
            As[(kb + 6) * 64 + lrow] = a1.z;
            As[(kb + 7) * 64 + lrow] = a1.w;
            Xs[(kb + 0) * 64 + lrow] = x0.x;
            Xs[(kb + 1) * 64 + lrow] = x0.y;
            Xs[(kb + 2) * 64 + lrow] = x0.z;
            Xs[(kb + 3) * 64 + lrow] = x0.w;
            Xs[(kb + 4) * 64 + lrow] = x1.x;
            Xs[(kb + 5) * 64 + lrow] = x1.y;
            Xs[(kb + 6) * 64 + lrow] = x1.z;
            Xs[(kb + 7) * 64 + lrow] = x1.w;
        }
        __syncthreads();

#pragma unroll 2
        for (int k = 0; k < 16; k++) {
            float4 a0 = *reinterpret_cast<float4*>(&As[k * 64 + ty * 8]);
            float4 a1 = *reinterpret_cast<float4*>(&As[k * 64 + ty * 8 + 4]);
            float4 x0 = *reinterpret_cast<float4*>(&Xs[k * 64 + ty * 8]);
            float4 x1 = *reinterpret_cast<float4*>(&Xs[k * 64 + ty * 8 + 4]);
            ulonglong2 L0 = *reinterpret_cast<ulonglong2*>(&Wls[k * 128 + tx * 8]);
            ulonglong2 L1 = *reinterpret_cast<ulonglong2*>(&Wls[k * 128 + tx * 8 + 4]);
            ulonglong2 R0 = *reinterpret_cast<ulonglong2*>(&Wrs[k * 128 + tx * 8]);
            ulonglong2 R1 = *reinterpret_cast<ulonglong2*>(&Wrs[k * 128 + tx * 8 + 4]);
            u64 lv[4] = {L0.x, L0.y, L1.x, L1.y};
            u64 rv[4] = {R0.x, R0.y, R1.x, R1.y};
            float av[8] = {a0.x, a0.y, a0.z, a0.w, a1.x, a1.y, a1.z, a1.w};
            float xv[8] = {x0.x, x0.y, x0.z, x0.w, x1.x, x1.y, x1.z, x1.w};
#pragma unroll
            for (int i = 0; i < 8; i++) {
                u64 ap2 = pk2(av[i]);
                u64 xp2 = pk2(xv[i]);
#pragma unroll
                for (int j = 0; j < 4; j++) {
                    fma2(acc[i][j], ap2, lv[j]);
                    fma2(acc[i][j], xp2, rv[j]);
                }
            }
        }
        __syncthreads();
    }

    float bias[8];
#pragma unroll
    for (int j = 0; j < 8; j++) bias[j] = __ldg(&bl[tx * 8 + j]);

#pragma unroll
    for (int i = 0; i < 8; i++) {
        float v[8];
        float ss = 0.f;
#pragma unroll
        for (int j = 0; j < 4; j++) {
            float2 t = up2(acc[i][j]);
            v[2 * j]     = t.x + bias[2 * j];
            v[2 * j + 1] = t.y + bias[2 * j + 1];
            ss = fmaf(v[2 * j], v[2 * j], ss);
            ss = fmaf(v[2 * j + 1], v[2 * j + 1], ss);
        }
#pragma unroll
        for (int m = 8; m >= 1; m >>= 1)
            ss += __shfl_xor_sync(0xffffffffu, ss, m, 16);
        float inv = 1.0f / fmaxf(sqrtf(ss), 1e-12f);
        int gr = row0 + ty * 8 + i;
        if (gr < n) {
            const float* hip = h_in + (size_t)gr * HD + tx * 8;
            float4 h0 = *reinterpret_cast<const float4*>(hip);
            float4 h1 = *reinterpret_cast<const float4*>(hip + 4);
            float o[8] = {h0.x, h0.y, h0.z, h0.w, h1.x, h1.y, h1.z, h1.w};
#pragma unroll
            for (int j = 0; j < 8; j++) o[j] += fmaxf(v[j] * inv, 0.0f);
            float* hop = h_out + (size_t)gr * HD + tx * 8;
            *reinterpret_cast<float4*>(hop)     = make_float4(o[0], o[1], o[2], o[3]);
            *reinterpret_cast<float4*>(hop + 4) = make_float4(o[4], o[5], o[6], o[7]);
        }
    }
}
static constexpr int SAGE_SMEM = (64 * AMS + 2048 + 2048 + 1024 + 1024) * 4; // 58368

// ---------------- register-tiled dense + relu (FFMA2) — encoders ----------------
template<int K, int N>
__global__ void __launch_bounds__(128) mlp_relu_kernel(
    const float* __restrict__ x, const float* __restrict__ W,
    const float* __restrict__ b, float* __restrict__ out, int n)
{
    constexpr int TX = N / 8;
    constexpr int TY = 128 / TX;
    constexpr int BM = TY * 8;
    __shared__ __align__(16) float Xs[16 * BM];
    __shared__ __align__(16) float Ws[16 * N];

    const int tid  = threadIdx.x;
    const int tx   = tid % TX;
    const int ty   = tid / TX;
    const int row0 = blockIdx.x * BM;

    u64 acc[8][4];
#pragma unroll
    for (int i = 0; i < 8; i++)
#pragma unroll
        for (int j = 0; j < 4; j++) acc[i][j] = 0ull;

#pragma unroll 1
    for (int kc = 0; kc < K / 16; kc++) {
        const int k0 = kc * 16;
#pragma unroll
        for (int i = tid; i < 16 * N / 4; i += 128)
            reinterpret_cast<float4*>(Ws)[i] =
                reinterpret_cast<const float4*>(W + (size_t)k0 * N)[i];
#pragma unroll
        for (int idx = tid; idx < BM * 2; idx += 128) {
            int r = idx >> 1, half = idx & 1;
            int gr = min(row0 + r, n - 1);
            const float* xp = x + (size_t)gr * K + k0 + half * 8;
            float4 x0 = *reinterpret_cast<const float4*>(xp);
            float4 x1 = *reinterpret_cast<const float4*>(xp + 4);
            int kb = half * 8;
            Xs[(kb + 0) * BM + r] = x0.x;
            Xs[(kb + 1) * BM + r] = x0.y;
            Xs[(kb + 2) * BM + r] = x0.z;
            Xs[(kb + 3) * BM + r] = x0.w;
            Xs[(kb + 4) * BM + r] = x1.x;
            Xs[(kb + 5) * BM + r] = x1.y;
            Xs[(kb + 6) * BM + r] = x1.z;
            Xs[(kb + 7) * BM + r] = x1.w;
        }
        __syncthreads();

#pragma unroll 2
        for (int k = 0; k < 16; k++) {
            float4 a0 = *reinterpret_cast<float4*>(&Xs[k * BM + ty * 8]);
            float4 a1 = *reinterpret_cast<float4*>(&Xs[k * BM + ty * 8 + 4]);
            ulonglong2 W0 = *reinterpret_cast<ulonglong2*>(&Ws[k * N + tx * 8]);
            ulonglong2 W1 = *reinterpret_cast<ulonglong2*>(&Ws[k * N + tx * 8 + 4]);
            u64 wv[4] = {W0.x, W0.y, W1.x, W1.y};
            float av[8] = {a0.x, a0.y, a0.z, a0.w, a1.x, a1.y, a1.z, a1.w};
#pragma unroll
            for (int i = 0; i < 8; i++) {
                u64 ap2 = pk2(av[i]);
#pragma unroll
                for (int j = 0; j < 4; j++)
                    fma2(acc[i][j], ap2, wv[j]);
            }
        }
        __syncthreads();
    }

    float bias[8];
#pragma unroll
    for (int j = 0; j < 8; j++) bias[j] = __ldg(&b[tx * 8 + j]);

#pragma unroll
    for (int i = 0; i < 8; i++) {
        int gr = row0 + ty * 8 + i;
        if (gr < n) {
            float o[8];
#pragma unroll
            for (int j = 0; j < 4; j++) {
                float2 t = up2(acc[i][j]);
                o[2 * j]     = fmaxf(t.x + bias[2 * j], 0.0f);
                o[2 * j + 1] = fmaxf(t.y + bias[2 * j + 1], 0.0f);
            }
            float* op = out + (size_t)gr * N + tx * 8;
            *reinterpret_cast<float4*>(op)     = make_float4(o[0], o[1], o[2], o[3]);
            *reinterpret_cast<float4*>(op + 4) = make_float4(o[4], o[5], o[6], o[7]);
        }
    }
}

// ---------------- fused head: out = relu(hu @ w1 + b1) @ w2 + b2 ----------------
__global__ void __launch_bounds__(128) head_fused_kernel(
    const float* __restrict__ x, const float* __restrict__ w1,
    const float* __restrict__ b1, const float* __restrict__ w2,
    const float* __restrict__ b2, float* __restrict__ out, int n)
{
    constexpr int N = 64, TX = 8, BM = 128;
    __shared__ __align__(16) float Xs[16 * BM];
    __shared__ __align__(16) float Ws[16 * N];
    __shared__ __align__(16) float Zs[BM * N];
    __shared__ __align__(16) float W2s[64 * 8];

    const int tid  = threadIdx.x;
    const int tx   = tid % TX;
    const int ty   = tid / TX;
    const int row0 = blockIdx.x * BM;

#pragma unroll
    for (int i = tid; i < 64 * 8 / 4; i += 128)
        reinterpret_cast<float4*>(W2s)[i] = reinterpret_cast<const float4*>(w2)[i];

    u64 acc[8][4];
#pragma unroll
    for (int i = 0; i < 8; i++)
#pragma unroll
        for (int j = 0; j < 4; j++) acc[i][j] = 0ull;

#pragma unroll 1
    for (int kc = 0; kc < 8; kc++) {
        const int k0 = kc * 16;
#pragma unroll
        for (int i = tid; i < 16 * N / 4; i += 128)
            reinterpret_cast<float4*>(Ws)[i] =
                reinterpret_cast<const float4*>(w1 + (size_t)k0 * N)[i];
#pragma unroll
        for (int idx = tid; idx < BM * 2; idx += 128) {
            int r = idx >> 1, half = idx & 1;
            int gr = min(row0 + r, n - 1);
            const float* xp = x + (size_t)gr * HD + k0 + half * 8;
            float4 x0 = *reinterpret_cast<const float4*>(xp);
            float4 x1 = *reinterpret_cast<const float4*>(xp + 4);
            int kb = half * 8;
            Xs[(kb + 0) * BM + r] = x0.x;
            Xs[(kb + 1) * BM + r] = x0.y;
            Xs[(kb + 2) * BM + r] = x0.z;
            Xs[(kb + 3) * BM + r] = x0.w;
            Xs[(kb + 4) * BM + r] = x1.x;
            Xs[(kb + 5) * BM + r] = x1.y;
            Xs[(kb + 6) * BM + r] = x1.z;
            Xs[(kb + 7) * BM + r] = x1.w;
        }
        __syncthreads();

#pragma unroll 2
        for (int k = 0; k < 16; k++) {
            float4 a0 = *reinterpret_cast<float4*>(&Xs[k * BM + ty * 8]);
            float4 a1 = *reinterpret_cast<float4*>(&Xs[k * BM + ty * 8 + 4]);
            ulonglong2 W0 = *reinterpret_cast<ulonglong2*>(&Ws[k * N + tx * 8]);
            ulonglong2 W1 = *reinterpret_cast<ulonglong2*>(&Ws[k * N + tx * 8 + 4]);
            u64 wv[4] = {W0.x, W0.y, W1.x, W1.y};
            float av[8] = {a0.x, a0.y, a0.z, a0.w, a1.x, a1.y, a1.z, a1.w};
#pragma unroll
            for (int i = 0; i < 8; i++) {
                u64 ap2 = pk2(av[i]);
#pragma unroll
                for (int j = 0; j < 4; j++)
                    fma2(acc[i][j], ap2, wv[j]);
            }
        }
        __syncthreads();
    }

    float bias[8];
#pragma unroll
    for (int j = 0; j < 8; j++) bias[j] = __ldg(&b1[tx * 8 + j]);

#pragma unroll
    for (int i = 0; i < 8; i++) {
        int r = ty * 8 + i;
        float o[8];
#pragma unroll
        for (int j = 0; j < 4; j++) {
            float2 t = up2(acc[i][j]);
            o[2 * j]     = fmaxf(t.x + bias[2 * j], 0.0f);
            o[2 * j + 1] = fmaxf(t.y + bias[2 * j + 1], 0.0f);
        }
        float* zp = &Zs[r * N + tx * 8];
        *reinterpret_cast<float4*>(zp)     = make_float4(o[0], o[1], o[2], o[3]);
        *reinterpret_cast<float4*>(zp + 4) = make_float4(o[4], o[5], o[6], o[7]);
    }
    __syncthreads();

    int gr = row0 + tid;
    if (gr < n) {
        float a2[8];
#pragma unroll
        for (int j = 0; j < 8; j++) a2[j] = __ldg(&b2[j]);
        const float* zr = &Zs[tid * N];
#pragma unroll
        for (int k = 0; k < 64; k++) {
            float zv = zr[k];
#pragma unroll
            for (int j = 0; j < 8; j++)
                a2[j] = fmaf(zv, W2s[k * 8 + j], a2[j]);
        }
        float* op = out + (size_t)gr * 8;
        *reinterpret_cast<float4*>(op)     = make_float4(a2[0], a2[1], a2[2], a2[3]);
        *reinterpret_cast<float4*>(op + 4) = make_float4(a2[4], a2[5], a2[6], a2[7]);
    }
}

// ---------------- stream/event resources (created once at static init) ----------------
struct GraphRes {
    cudaStream_t s1;
    cudaEvent_t ev0, ev_enc, ev_csr, ev_u1;
    GraphRes() {
        cudaStreamCreateWithFlags(&s1, cudaStreamNonBlocking);
        cudaEventCreateWithFlags(&ev0,    cudaEventDisableTiming);
        cudaEventCreateWithFlags(&ev_enc, cudaEventDisableTiming);
        cudaEventCreateWithFlags(&ev_csr, cudaEventDisableTiming);
        cudaEventCreateWithFlags(&ev_u1,  cudaEventDisableTiming);
    }
};
static GraphRes g_res;

// ---------------- launch ----------------
static float* sym_addr_f(const void* sym) {
    void* p = nullptr;
    cudaGetSymbolAddress(&p, sym);
    return reinterpret_cast<float*>(p);
}
static int* sym_addr_i(const void* sym) {
    void* p = nullptr;
    cudaGetSymbolAddress(&p, sym);
    return reinterpret_cast<int*>(p);
}

extern "C" void kernel_launch(void* const* d_in, const int* in_sizes, int n_in,
                              void* d_out, int out_size)
{
    const float* x_user  = (const float*)d_in[0];
    const float* x_item  = (const float*)d_in[1];
    const int*   ei_u2i  = (const int*)d_in[2];
    const int*   ei_i2u  = (const int*)d_in[3];
    const float* enc_uw  = (const float*)d_in[4];
    const float* enc_ub  = (const float*)d_in[5];
    const float* enc_iw  = (const float*)d_in[6];
    const float* enc_ib  = (const float*)d_in[7];
    const float* L[12];
    for (int i = 0; i < 12; i++) L[i] = (const float*)d_in[8 + i];
    const float* head_w1 = (const float*)d_in[20];
    const float* head_b1 = (const float*)d_in[21];
    const float* head_w2 = (const float*)d_in[22];
    const float* head_b2 = (const float*)d_in[23];
    float* out = (float*)d_out;

    float* hu  = sym_addr_f(g_hu);
    float* hi  = sym_addr_f(g_hi);
    float* hu2 = sym_addr_f(g_hu2);
    float* hi2 = sym_addr_f(g_hi2);
    float* hu3 = sym_addr_f(g_hu3);

    int* deg    = sym_addr_i(g_deg);
    int* rowptr = sym_addr_i(g_rowptr);
    int* fill   = sym_addr_i(g_fill);
    int* bsums  = sym_addr_i(g_bsums);
    int* esrc   = sym_addr_i(g_esrc);

    cudaFuncSetAttribute(sage_fused_kernel,
                         cudaFuncAttributeMaxDynamicSharedMemorySize, SAGE_SMEM);

    cudaStream_t s1 = g_res.s1;
    const int EBV = (NE + 255) / 256;
    const int NB1 = (NN + 1023) / 1024;

    // ---- fork: encoders on s1, CSR build on main ----
    cudaEventRecord(g_res.ev0, 0);
    cudaStreamWaitEvent(s1, g_res.ev0, 0);

    mlp_relu_kernel<64, 128><<<(NU + 63) / 64, 128, 0, s1>>>(x_user, enc_uw, enc_ub, hu, NU);
    mlp_relu_kernel<32, 128><<<(NI + 63) / 64, 128, 0, s1>>>(x_item, enc_iw, enc_ib, hi, NI);
    cudaEventRecord(g_res.ev_enc, s1);

    zero_kernel<<<(NN / 4 + 255) / 256, 256>>>((float4*)deg, NN / 4);
    hist2_kernel<<<EBV, 256>>>(ei_u2i, ei_i2u, deg);
    scan1_kernel<<<NB1, 1024>>>(deg, rowptr, bsums, NN);
    scan2_kernel<<<1, 1024>>>(bsums, NB1);
    scan3_kernel<<<(NN + 255) / 256, 256>>>(rowptr, fill, bsums, NN, 2 * NE);
    fill2_kernel<<<EBV, 256>>>(ei_u2i, ei_i2u, fill, esrc);
    cudaEventRecord(g_res.ev_csr, 0);

    // ---- layer 1: fused item update on main (needs encoders + CSR) ----
    cudaStreamWaitEvent(0, g_res.ev_enc, 0);
    sage_fused_kernel<<<(NI + 63) / 64, 128, SAGE_SMEM>>>(
        hu, hi, hi2, rowptr, esrc, L[0], L[1], L[2], NI);

    // ---- layer 1: fused user update on s1, concurrent with item update ----
    cudaStreamWaitEvent(s1, g_res.ev_csr, 0);
    sage_fused_kernel<<<(NU + 63) / 64, 128, SAGE_SMEM, s1>>>(
        hi, hu, hu2, rowptr + NI, esrc, L[3], L[4], L[5], NU);
    cudaEventRecord(g_res.ev_u1, s1);

    // ---- layer 2: fused user update (needs hi2 from main order + hu2 from s1) ----
    cudaStreamWaitEvent(0, g_res.ev_u1, 0);
    sage_fused_kernel<<<(NU + 63) / 64, 128, SAGE_SMEM>>>(
        hi2, hu2, hu3, rowptr + NI, esrc, L[9], L[10], L[11], NU);

    // ---- fused head ----
    head_fused_kernel<<<(NU + 127) / 128, 128>>>(hu3, head_w1, head_b1, head_w2, head_b2, out, NU);
}

// round 13
// speedup vs baseline: 1.2839x; 1.2839x over previous
#include <cuda_runtime.h>
#include <cuda_bf16.h>
#include <cstdint>

#define NU 50000
#define NI 50000
#define NE 800000
#define HD 128
#define NN (NI + NU)

typedef unsigned long long u64;

// ---------------- f32x2 packed-FMA helpers (Blackwell FFMA2) ----------------
__device__ __forceinline__ u64 pk2(float v) {
    u64 r; asm("mov.b64 %0, {%1,%1};" : "=l"(r) : "f"(v)); return r;
}
__device__ __forceinline__ void fma2(u64& d, u64 a, u64 b) {
    asm("fma.rn.f32x2 %0, %1, %2, %3;" : "=l"(d) : "l"(a), "l"(b), "l"(d));
}
__device__ __forceinline__ float2 up2(u64 v) {
    float2 f; asm("mov.b64 {%0,%1}, %2;" : "=f"(f.x), "=f"(f.y) : "l"(v)); return f;
}

// ---------------- device scratch ----------------
__device__ __align__(16) float g_hu [(size_t)NU * HD];
__device__ __align__(16) float g_hi [(size_t)NI * HD];
__device__ __align__(16) float g_agg[(size_t)NN * HD];   // layer-1 [agg_item | agg_user]
__device__ __align__(16) float g_aggu2[(size_t)NU * HD]; // layer-2 user agg (no reuse race)

__device__ __align__(16) int g_deg[NN];
__device__ __align__(16) int g_rowptr[NN + 1];
__device__ __align__(16) int g_fill[NN];
__device__ __align__(16) int g_bsums[128];
__device__ __align__(16) int g_esrc[2 * NE];

// ---------------- zero ----------------
__global__ void zero_kernel(float4* __restrict__ p, int n4) {
    int i = blockIdx.x * blockDim.x + threadIdx.x;
    if (i < n4) p[i] = make_float4(0.f, 0.f, 0.f, 0.f);
}

// ---------------- CSR: histogram over both relations (2 edges/thread) ----------------
__global__ void hist2_kernel(const int* __restrict__ ei_a, const int* __restrict__ ei_b,
                             int* __restrict__ deg)
{
    int t = blockIdx.x * blockDim.x + threadIdx.x;
    if (t < NE / 2) {
        int2 d = *reinterpret_cast<const int2*>(ei_a + NE + 2 * t);
        atomicAdd(&deg[d.x], 1);
        atomicAdd(&deg[d.y], 1);
    } else if (t < NE) {
        int2 d = *reinterpret_cast<const int2*>(ei_b + NE + 2 * (t - NE / 2));
        atomicAdd(&deg[NI + d.x], 1);
        atomicAdd(&deg[NI + d.y], 1);
    }
}

// ---------------- CSR: two-level scan ----------------
__global__ void __launch_bounds__(1024) scan1_kernel(
    const int* __restrict__ deg, int* __restrict__ rowptr, int* __restrict__ bsums, int n)
{
    __shared__ int ws[32];
    const int tid = threadIdx.x, lane = tid & 31, wid = tid >> 5;
    int i = blockIdx.x * 1024 + tid;
    int v = (i < n) ? deg[i] : 0;
    int x = v;
#pragma unroll
    for (int off = 1; off < 32; off <<= 1) {
        int y = __shfl_up_sync(0xffffffffu, x, off);
        if (lane >= off) x += y;
    }
    if (lane == 31) ws[wid] = x;
    __syncthreads();
    if (tid < 32) {
        int s = ws[tid];
#pragma unroll
        for (int off = 1; off < 32; off <<= 1) {
            int y = __shfl_up_sync(0xffffffffu, s, off);
            if (tid >= off) s += y;
        }
        ws[tid] = s;
    }
    __syncthreads();
    int prev = wid ? ws[wid - 1] : 0;
    if (i < n) rowptr[i] = prev + x - v;
    if (tid == 1023) bsums[blockIdx.x] = prev + x;
}

__global__ void __launch_bounds__(1024) scan2_kernel(int* __restrict__ data, int n) {
    __shared__ int ws[32];
    const int tid = threadIdx.x, lane = tid & 31, wid = tid >> 5;
    int v = (tid < n) ? data[tid] : 0;
    int x = v;
#pragma unroll
    for (int off = 1; off < 32; off <<= 1) {
        int y = __shfl_up_sync(0xffffffffu, x, off);
        if (lane >= off) x += y;
    }
    if (lane == 31) ws[wid] = x;
    __syncthreads();
    if (tid < 32) {
        int s = ws[tid];
#pragma unroll
        for (int off = 1; off < 32; off <<= 1) {
            int y = __shfl_up_sync(0xffffffffu, s, off);
            if (tid >= off) s += y;
        }
        ws[tid] = s;
    }
    __syncthreads();
    int prev = wid ? ws[wid - 1] : 0;
    if (tid < n) data[tid] = prev + x - v;
}

__global__ void scan3_kernel(int* __restrict__ rowptr, int* __restrict__ fill,
                             const int* __restrict__ bsums, int n, int total)
{
    int i = blockIdx.x * blockDim.x + threadIdx.x;
    if (i < n) {
        int v = rowptr[i] + bsums[i >> 10];
        rowptr[i] = v;
        fill[i] = v;
    }
    if (i == 0) rowptr[n] = total;
}

// ---------------- CSR: fill edge-source buckets (2 edges/thread) ----------------
__global__ void fill2_kernel(const int* __restrict__ ei_a, const int* __restrict__ ei_b,
                             int* __restrict__ cursor, int* __restrict__ esrc)
{
    int t = blockIdx.x * blockDim.x + threadIdx.x;
    if (t < NE / 2) {
        int e = 2 * t;
        int2 d = *reinterpret_cast<const int2*>(ei_a + NE + e);
        int2 s = *reinterpret_cast<const int2*>(ei_a + e);
        esrc[atomicAdd(&cursor[d.x], 1)] = s.x;
        esrc[atomicAdd(&cursor[d.y], 1)] = s.y;
    } else if (t < NE) {
        int e = 2 * (t - NE / 2);
        int2 d = *reinterpret_cast<const int2*>(ei_b + NE + e);
        int2 s = *reinterpret_cast<const int2*>(ei_b + e);
        esrc[atomicAdd(&cursor[NI + d.x], 1)] = s.x;
        esrc[atomicAdd(&cursor[NI + d.y], 1)] = s.y;
    }
}

// ---------------- gather mean: one warp per dst node; node<split reads srcA else srcB ----
__global__ void __launch_bounds__(256) gather_mean_kernel(
    const float* __restrict__ srcA, const float* __restrict__ srcB,
    const int* __restrict__ rowptr, const int* __restrict__ esrc,
    float* __restrict__ agg, int n, int split)
{
    int node = (blockIdx.x * blockDim.x + threadIdx.x) >> 5;
    int lane = threadIdx.x & 31;
    if (node >= n) return;
    const float* src_feat = (node < split) ? srcA : srcB;
    int beg = __ldg(&rowptr[node]);
    int end = __ldg(&rowptr[node + 1]);
    float4 acc = make_float4(0.f, 0.f, 0.f, 0.f);
    int e = beg;
    // 8-edge unrolled main loop for deeper MLP
    for (; e + 8 <= end; e += 8) {
        int s[8];
#pragma unroll
        for (int q = 0; q < 8; q++) s[q] = __ldg(&esrc[e + q]);
        float4 v[8];
#pragma unroll
        for (int q = 0; q < 8; q++)
            v[q] = reinterpret_cast<const float4*>(src_feat + (size_t)s[q] * HD)[lane];
#pragma unroll
        for (int q = 0; q < 8; q++) {
            acc.x += v[q].x; acc.y += v[q].y; acc.z += v[q].z; acc.w += v[q].w;
        }
    }
    for (; e + 2 <= end; e += 2) {
        int s0 = __ldg(&esrc[e]);
        int s1 = __ldg(&esrc[e + 1]);
        float4 v0 = reinterpret_cast<const float4*>(src_feat + (size_t)s0 * HD)[lane];
        float4 v1 = reinterpret_cast<const float4*>(src_feat + (size_t)s1 * HD)[lane];
        acc.x += v0.x + v1.x; acc.y += v0.y + v1.y;
        acc.z += v0.z + v1.z; acc.w += v0.w + v1.w;
    }
    if (e < end) {
        int s = __ldg(&esrc[e]);
        float4 v = reinterpret_cast<const float4*>(src_feat + (size_t)s * HD)[lane];
        acc.x += v.x; acc.y += v.y; acc.z += v.z; acc.w += v.w;
    }
    float inv = 1.0f / fmaxf((float)(end - beg), 1.0f);
    acc.x *= inv; acc.y *= inv; acc.z *= inv; acc.w *= inv;
    reinterpret_cast<float4*>(agg + (size_t)node * HD)[lane] = acc;
}

// ---------------- fused SAGE combine (FFMA2), in-place ----------------
// h[r] = relu( L2norm(agg[r] @ Wl + bl + h[r] @ Wr) ) + h[r]
__global__ void __launch_bounds__(128) combine_kernel(
    const float* __restrict__ agg, float* __restrict__ h,
    const float* __restrict__ wl, const float* __restrict__ bl,
    const float* __restrict__ wr, int n)
{
    __shared__ __align__(16) float As[16 * 64];
    __shared__ __align__(16) float Xs[16 * 64];
    __shared__ __align__(16) float Wls[16 * 128];
    __shared__ __align__(16) float Wrs[16 * 128];

    const int tid  = threadIdx.x;
    const int tx   = tid & 15;
    const int ty   = tid >> 4;
    const int row0 = blockIdx.x * 64;

    u64 acc[8][4];
#pragma unroll
    for (int i = 0; i < 8; i++)
#pragma unroll
        for (int j = 0; j < 4; j++) acc[i][j] = 0ull;

    const int lrow  = tid >> 1;
    const int lhalf = tid & 1;
    const int grow  = min(row0 + lrow, n - 1);

    for (int kc = 0; kc < 8; kc++) {
        const int k0 = kc * 16;
        {
            const float4* sl = reinterpret_cast<const float4*>(wl + k0 * 128);
            const float4* sr = reinterpret_cast<const float4*>(wr + k0 * 128);
            float4* dl = reinterpret_cast<float4*>(Wls);
            float4* dr = reinterpret_cast<float4*>(Wrs);
#pragma unroll
            for (int i = 0; i < 4; i++) {
                dl[tid + i * 128] = sl[tid + i * 128];
                dr[tid + i * 128] = sr[tid + i * 128];
            }
        }
        {
            const float* ap = agg + (size_t)grow * HD + k0 + lhalf * 8;
            const float* xp = h   + (size_t)grow * HD + k0 + lhalf * 8;
            float4 a0 = *reinterpret_cast<const float4*>(ap);
            float4 a1 = *reinterpret_cast<const float4*>(ap + 4);
            float4 x0 = *reinterpret_cast<const float4*>(xp);
            float4 x1 = *reinterpret_cast<const float4*>(xp + 4);
            int kb = lhalf * 8;
            As[(kb + 0) * 64 + lrow] = a0.x;
            As[(kb + 1) * 64 + lrow] = a0.y;
            As[(kb + 2) * 64 + lrow] = a0.z;
            As[(kb + 3) * 64 + lrow] = a0.w;
            As[(kb + 4) * 64 + lrow] = a1.x;
            As[(kb + 5) * 64 + lrow] = a1.y;
            As[(kb + 6) * 64 + lrow] = a1.z;
            As[(kb + 7) * 64 + lrow] = a1.w;
            Xs[(kb + 0) * 64 + lrow] = x0.x;
            Xs[(kb + 1) * 64 + lrow] = x0.y;
            Xs[(kb + 2) * 64 + lrow] = x0.z;
            Xs[(kb + 3) * 64 + lrow] = x0.w;
            Xs[(kb + 4) * 64 + lrow] = x1.x;
            Xs[(kb + 5) * 64 + lrow] = x1.y;
            Xs[(kb + 6) * 64 + lrow] = x1.z;
            Xs[(kb + 7) * 64 + lrow] = x1.w;
        }
        __syncthreads();

#pragma unroll 2
        for (int k = 0; k < 16; k++) {
            float4 a0 = *reinterpret_cast<float4*>(&As[k * 64 + ty * 8]);
            float4 a1 = *reinterpret_cast<float4*>(&As[k * 64 + ty * 8 + 4]);
            float4 x0 = *reinterpret_cast<float4*>(&Xs[k * 64 + ty * 8]);
            float4 x1 = *reinterpret_cast<float4*>(&Xs[k * 64 + ty * 8 + 4]);
            ulonglong2 L0 = *reinterpret_cast<ulonglong2*>(&Wls[k * 128 + tx * 8]);
            ulonglong2 L1 = *reinterpret_cast<ulonglong2*>(&Wls[k * 128 + tx * 8 + 4]);
            ulonglong2 R0 = *reinterpret_cast<ulonglong2*>(&Wrs[k * 128 + tx * 8]);
            ulonglong2 R1 = *reinterpret_cast<ulonglong2*>(&Wrs[k * 128 + tx * 8 + 4]);
            u64 lv[4] = {L0.x, L0.y, L1.x, L1.y};
            u64 rv[4] = {R0.x, R0.y, R1.x, R1.y};
            float av[8] = {a0.x, a0.y, a0.z, a0.w, a1.x, a1.y, a1.z, a1.w};
            float xv[8] = {x0.x, x0.y, x0.z, x0.w, x1.x, x1.y, x1.z, x1.w};
#pragma unroll
            for (int i = 0; i < 8; i++) {
                u64 ap2 = pk2(av[i]);
                u64 xp2 = pk2(xv[i]);
#pragma unroll
                for (int j = 0; j < 4; j++) {
                    fma2(acc[i][j], ap2, lv[j]);
                    fma2(acc[i][j], xp2, rv[j]);
                }
            }
        }
        __syncthreads();
    }

    float bias[8];
#pragma unroll
    for (int j = 0; j < 8; j++) bias[j] = __ldg(&bl[tx * 8 + j]);

#pragma unroll
    for (int i = 0; i < 8; i++) {
        float v[8];
        float ss = 0.f;
#pragma unroll
        for (int j = 0; j < 4; j++) {
            float2 t = up2(acc[i][j]);
            v[2 * j]     = t.x + bias[2 * j];
            v[2 * j + 1] = t.y + bias[2 * j + 1];
            ss = fmaf(v[2 * j], v[2 * j], ss);
            ss = fmaf(v[2 * j + 1], v[2 * j + 1], ss);
        }
#pragma unroll
        for (int m = 8; m >= 1; m >>= 1)
            ss += __shfl_xor_sync(0xffffffffu, ss, m, 16);
        float inv = 1.0f / fmaxf(sqrtf(ss), 1e-12f);
        int gr = row0 + ty * 8 + i;
        if (gr < n) {
            float* hp = h + (size_t)gr * HD + tx * 8;
            float4 h0 = *reinterpret_cast<float4*>(hp);
            float4 h1 = *reinterpret_cast<float4*>(hp + 4);
            float o[8] = {h0.x, h0.y, h0.z, h0.w, h1.x, h1.y, h1.z, h1.w};
#pragma unroll
            for (int j = 0; j < 8; j++) o[j] += fmaxf(v[j] * inv, 0.0f);
            *reinterpret_cast<float4*>(hp)     = make_float4(o[0], o[1], o[2], o[3]);
            *reinterpret_cast<float4*>(hp + 4) = make_float4(o[4], o[5], o[6], o[7]);
        }
    }
}

// ---------------- register-tiled dense + relu (FFMA2) — encoders ----------------
template<int K, int N>
__global__ void __launch_bounds__(128) mlp_relu_kernel(
    const float* __restrict__ x, const float* __restrict__ W,
    const float* __restrict__ b, float* __restrict__ out, int n)
{
    constexpr int TX = N / 8;
    constexpr int TY = 128 / TX;
    constexpr int BM = TY * 8;
    __shared__ __align__(16) float Xs[16 * BM];
    __shared__ __align__(16) float Ws[16 * N];

    const int tid  = threadIdx.x;
    const int tx   = tid % TX;
    const int ty   = tid / TX;
    const int row0 = blockIdx.x * BM;

    u64 acc[8][4];
#pragma unroll
    for (int i = 0; i < 8; i++)
#pragma unroll
        for (int j = 0; j < 4; j++) acc[i][j] = 0ull;

#pragma unroll 1
    for (int kc = 0; kc < K / 16; kc++) {
        const int k0 = kc * 16;
#pragma unroll
        for (int i = tid; i < 16 * N / 4; i += 128)
            reinterpret_cast<float4*>(Ws)[i] =
                reinterpret_cast<const float4*>(W + (size_t)k0 * N)[i];
#pragma unroll
        for (int idx = tid; idx < BM * 2; idx += 128) {
            int r = idx >> 1, half = idx & 1;
            int gr = min(row0 + r, n - 1);
            const float* xp = x + (size_t)gr * K + k0 + half * 8;
            float4 x0 = *reinterpret_cast<const float4*>(xp);
            float4 x1 = *reinterpret_cast<const float4*>(xp + 4);
            int kb = half * 8;
            Xs[(kb + 0) * BM + r] = x0.x;
            Xs[(kb + 1) * BM + r] = x0.y;
            Xs[(kb + 2) * BM + r] = x0.z;
            Xs[(kb + 3) * BM + r] = x0.w;
            Xs[(kb + 4) * BM + r] = x1.x;
            Xs[(kb + 5) * BM + r] = x1.y;
            Xs[(kb + 6) * BM + r] = x1.z;
            Xs[(kb + 7) * BM + r] = x1.w;
        }
        __syncthreads();

#pragma unroll 2
        for (int k = 0; k < 16; k++) {
            float4 a0 = *reinterpret_cast<float4*>(&Xs[k * BM + ty * 8]);
            float4 a1 = *reinterpret_cast<float4*>(&Xs[k * BM + ty * 8 + 4]);
            ulonglong2 W0 = *reinterpret_cast<ulonglong2*>(&Ws[k * N + tx * 8]);
            ulonglong2 W1 = *reinterpret_cast<ulonglong2*>(&Ws[k * N + tx * 8 + 4]);
            u64 wv[4] = {W0.x, W0.y, W1.x, W1.y};
            float av[8] = {a0.x, a0.y, a0.z, a0.w, a1.x, a1.y, a1.z, a1.w};
#pragma unroll
            for (int i = 0; i < 8; i++) {
                u64 ap2 = pk2(av[i]);
#pragma unroll
                for (int j = 0; j < 4; j++)
                    fma2(acc[i][j], ap2, wv[j]);
            }
        }
        __syncthreads();
    }

    float bias[8];
#pragma unroll
    for (int j = 0; j < 8; j++) bias[j] = __ldg(&b[tx * 8 + j]);

#pragma unroll
    for (int i = 0; i < 8; i++) {
        int gr = row0 + ty * 8 + i;
        if (gr < n) {
            float o[8];
#pragma unroll
            for (int j = 0; j < 4; j++) {
                float2 t = up2(acc[i][j]);
                o[2 * j]     = fmaxf(t.x + bias[2 * j], 0.0f);
                o[2 * j + 1] = fmaxf(t.y + bias[2 * j + 1], 0.0f);
            }
            float* op = out + (size_t)gr * N + tx * 8;
            *reinterpret_cast<float4*>(op)     = make_float4(o[0], o[1], o[2], o[3]);
            *reinterpret_cast<float4*>(op + 4) = make_float4(o[4], o[5], o[6], o[7]);
        }
    }
}

// ---------------- fused head: out = relu(hu @ w1 + b1) @ w2 + b2 ----------------
__global__ void __launch_bounds__(128) head_fused_kernel(
    const float* __restrict__ x, const float* __restrict__ w1,
    const float* __restrict__ b1, const float* __restrict__ w2,
    const float* __restrict__ b2, float* __restrict__ out, int n)
{
    constexpr int N = 64, TX = 8, BM = 128;
    __shared__ __align__(16) float Xs[16 * BM];
    __shared__ __align__(16) float Ws[16 * N];
    __shared__ __align__(16) float Zs[BM * N];
    __shared__ __align__(16) float W2s[64 * 8];

    const int tid  = threadIdx.x;
    const int tx   = tid % TX;
    const int ty   = tid / TX;
    const int row0 = blockIdx.x * BM;

#pragma unroll
    for (int i = tid; i < 64 * 8 / 4; i += 128)
        reinterpret_cast<float4*>(W2s)[i] = reinterpret_cast<const float4*>(w2)[i];

    u64 acc[8][4];
#pragma unroll
    for (int i = 0; i < 8; i++)
#pragma unroll
        for (int j = 0; j < 4; j++) acc[i][j] = 0ull;

#pragma unroll 1
    for (int kc = 0; kc < 8; kc++) {
        const int k0 = kc * 16;
#pragma unroll
        for (int i = tid; i < 16 * N / 4; i += 128)
            reinterpret_cast<float4*>(Ws)[i] =
                reinterpret_cast<const float4*>(w1 + (size_t)k0 * N)[i];
#pragma unroll
        for (int idx = tid; idx < BM * 2; idx += 128) {
            int r = idx >> 1, half = idx & 1;
            int gr = min(row0 + r, n - 1);
            const float* xp = x + (size_t)gr * HD + k0 + half * 8;
            float4 x0 = *reinterpret_cast<const float4*>(xp);
            float4 x1 = *reinterpret_cast<const float4*>(xp + 4);
            int kb = half * 8;
            Xs[(kb + 0) * BM + r] = x0.x;
            Xs[(kb + 1) * BM + r] = x0.y;
            Xs[(kb + 2) * BM + r] = x0.z;
            Xs[(kb + 3) * BM + r] = x0.w;
            Xs[(kb + 4) * BM + r] = x1.x;
            Xs[(kb + 5) * BM + r] = x1.y;
            Xs[(kb + 6) * BM + r] = x1.z;
            Xs[(kb + 7) * BM + r] = x1.w;
        }
        __syncthreads();

#pragma unroll 2
        for (int k = 0; k < 16; k++) {
            float4 a0 = *reinterpret_cast<float4*>(&Xs[k * BM + ty * 8]);
            float4 a1 = *reinterpret_cast<float4*>(&Xs[k * BM + ty * 8 + 4]);
            ulonglong2 W0 = *reinterpret_cast<ulonglong2*>(&Ws[k * N + tx * 8]);
            ulonglong2 W1 = *reinterpret_cast<ulonglong2*>(&Ws[k * N + tx * 8 + 4]);
            u64 wv[4] = {W0.x, W0.y, W1.x, W1.y};
            float av[8] = {a0.x, a0.y, a0.z, a0.w, a1.x, a1.y, a1.z, a1.w};
#pragma unroll
            for (int i = 0; i < 8; i++) {
                u64 ap2 = pk2(av[i]);
#pragma unroll
                for (int j = 0; j < 4; j++)
                    fma2(acc[i][j], ap2, wv[j]);
            }
        }
        __syncthreads();
    }

    float bias[8];
#pragma unroll
    for (int j = 0; j < 8; j++) bias[j] = __ldg(&b1[tx * 8 + j]);

#pragma unroll
    for (int i = 0; i < 8; i++) {
        int r = ty * 8 + i;
        float o[8];
#pragma unroll
        for (int j = 0; j < 4; j++) {
            float2 t = up2(acc[i][j]);
            o[2 * j]     = fmaxf(t.x + bias[2 * j], 0.0f);
            o[2 * j + 1] = fmaxf(t.y + bias[2 * j + 1], 0.0f);
        }
        float* zp = &Zs[r * N + tx * 8];
        *reinterpret_cast<float4*>(zp)     = make_float4(o[0], o[1], o[2], o[3]);
        *reinterpret_cast<float4*>(zp + 4) = make_float4(o[4], o[5], o[6], o[7]);
    }
    __syncthreads();

    int gr = row0 + tid;
    if (gr < n) {
        float a2[8];
#pragma unroll
        for (int j = 0; j < 8; j++) a2[j] = __ldg(&b2[j]);
        const float* zr = &Zs[tid * N];
#pragma unroll
        for (int k = 0; k < 64; k++) {
            float zv = zr[k];
#pragma unroll
            for (int j = 0; j < 8; j++)
                a2[j] = fmaf(zv, W2s[k * 8 + j], a2[j]);
        }
        float* op = out + (size_t)gr * 8;
        *reinterpret_cast<float4*>(op)     = make_float4(a2[0], a2[1], a2[2], a2[3]);
        *reinterpret_cast<float4*>(op + 4) = make_float4(a2[4], a2[5], a2[6], a2[7]);
    }
}

// ---------------- stream/event resources (created once at static init) ----------------
struct GraphRes {
    cudaStream_t s1;
    cudaEvent_t ev0, ev_enc, ev_fork, ev_cu1;
    GraphRes() {
        cudaStreamCreateWithFlags(&s1, cudaStreamNonBlocking);
        cudaEventCreateWithFlags(&ev0,    cudaEventDisableTiming);
        cudaEventCreateWithFlags(&ev_enc, cudaEventDisableTiming);
        cudaEventCreateWithFlags(&ev_fork, cudaEventDisableTiming);
        cudaEventCreateWithFlags(&ev_cu1, cudaEventDisableTiming);
    }
};
static GraphRes g_res;

// ---------------- launch ----------------
static float* sym_addr_f(const void* sym) {
    void* p = nullptr;
    cudaGetSymbolAddress(&p, sym);
    return reinterpret_cast<float*>(p);
}
static int* sym_addr_i(const void* sym) {
    void* p = nullptr;
    cudaGetSymbolAddress(&p, sym);
    return reinterpret_cast<int*>(p);
}

extern "C" void kernel_launch(void* const* d_in, const int* in_sizes, int n_in,
                              void* d_out, int out_size)
{
    const float* x_user  = (const float*)d_in[0];
    const float* x_item  = (const float*)d_in[1];
    const int*   ei_u2i  = (const int*)d_in[2];
    const int*   ei_i2u  = (const int*)d_in[3];
    const float* enc_uw  = (const float*)d_in[4];
    const float* enc_ub  = (const float*)d_in[5];
    const float* enc_iw  = (const float*)d_in[6];
    const float* enc_ib  = (const float*)d_in[7];
    const float* L[12];
    for (int i = 0; i < 12; i++) L[i] = (const float*)d_in[8 + i];
    const float* head_w1 = (const float*)d_in[20];
    const float* head_b1 = (const float*)d_in[21];
    const float* head_w2 = (const float*)d_in[22];
    const float* head_b2 = (const float*)d_in[23];
    float* out = (float*)d_out;

    float* hu     = sym_addr_f(g_hu);
    float* hi     = sym_addr_f(g_hi);
    float* agg    = sym_addr_f(g_agg);
    float* agg_i  = agg;
    float* agg_u  = agg + (size_t)NI * HD;
    float* agg_u2 = sym_addr_f(g_aggu2);

    int* deg    = sym_addr_i(g_deg);
    int* rowptr = sym_addr_i(g_rowptr);
    int* fill   = sym_addr_i(g_fill);
    int* bsums  = sym_addr_i(g_bsums);
    int* esrc   = sym_addr_i(g_esrc);

    cudaStream_t s1 = g_res.s1;
    const int EBV = (NE + 255) / 256;
    const int NB1 = (NN + 1023) / 1024;

    // ---- fork: encoders on s1, CSR build on main ----
    cudaEventRecord(g_res.ev0, 0);
    cudaStreamWaitEvent(s1, g_res.ev0, 0);

    mlp_relu_kernel<64, 128><<<(NU + 63) / 64, 128, 0, s1>>>(x_user, enc_uw, enc_ub, hu, NU);
    mlp_relu_kernel<32, 128><<<(NI + 63) / 64, 128, 0, s1>>>(x_item, enc_iw, enc_ib, hi, NI);
    cudaEventRecord(g_res.ev_enc, s1);

    zero_kernel<<<(NN / 4 + 255) / 256, 256>>>((float4*)deg, NN / 4);
    hist2_kernel<<<EBV, 256>>>(ei_u2i, ei_i2u, deg);
    scan1_kernel<<<NB1, 1024>>>(deg, rowptr, bsums, NN);
    scan2_kernel<<<1, 1024>>>(bsums, NB1);
    scan3_kernel<<<(NN + 255) / 256, 256>>>(rowptr, fill, bsums, NN, 2 * NE);
    fill2_kernel<<<EBV, 256>>>(ei_u2i, ei_i2u, fill, esrc);

    // join: gathers need both encoders and CSR
    cudaStreamWaitEvent(0, g_res.ev_enc, 0);

    // ---- layer 1: both gathers in one launch (items read hu, users read hi) ----
    gather_mean_kernel<<<(NN * 32 + 255) / 256, 256>>>(hu, hi, rowptr, esrc, agg, NN, NI);

    // fork: c_u1 on s1 (reads agg_u + hu, in-place on hu)
    cudaEventRecord(g_res.ev_fork, 0);
    cudaStreamWaitEvent(s1, g_res.ev_fork, 0);
    combine_kernel<<<(NU + 63) / 64, 128, 0, s1>>>(agg_u, hu, L[3], L[4], L[5], NU);
    cudaEventRecord(g_res.ev_cu1, s1);

    // main: c_i1 (in-place on hi), then layer-2 user gather (reads updated hi)
    combine_kernel<<<(NI + 63) / 64, 128>>>(agg_i, hi, L[0], L[1], L[2], NI);
    gather_mean_kernel<<<(NU * 32 + 255) / 256, 256>>>(hi, hi, rowptr + NI, esrc, agg_u2, NU, 0);

    // join: c_u2 needs agg_u2 (main) + updated hu (s1)
    cudaStreamWaitEvent(0, g_res.ev_cu1, 0);

    // ---- layer 2: only the user path feeds the head (item update is dead code) ----
    combine_kernel<<<(NU + 63) / 64, 128>>>(agg_u2, hu, L[9], L[10], L[11], NU);

    // ---- fused head ----
    head_fused_kernel<<<(NU + 127) / 128, 128>>>(hu, head_w1, head_b1, head_w2, head_b2, out, NU);
}

// round 14
// speedup vs baseline: 1.3032x; 1.0151x over previous
#include <cuda_runtime.h>
#include <cuda_bf16.h>
#include <cstdint>

#define NU 50000
#define NI 50000
#define NE 800000
#define HD 128
#define NN (NI + NU)

typedef unsigned long long u64;

// ---------------- f32x2 packed-FMA helpers (Blackwell FFMA2) ----------------
__device__ __forceinline__ u64 pk2(float v) {
    u64 r; asm("mov.b64 %0, {%1,%1};" : "=l"(r) : "f"(v)); return r;
}
__device__ __forceinline__ void fma2(u64& d, u64 a, u64 b) {
    asm("fma.rn.f32x2 %0, %1, %2, %3;" : "=l"(d) : "l"(a), "l"(b), "l"(d));
}
__device__ __forceinline__ float2 up2(u64 v) {
    float2 f; asm("mov.b64 {%0,%1}, %2;" : "=f"(f.x), "=f"(f.y) : "l"(v)); return f;
}

// ---------------- bf16 pack/unpack helpers ----------------
__device__ __forceinline__ void store_bf16x8(__nv_bfloat16* p, const float* o) {
    __nv_bfloat162 b0 = __float22bfloat162_rn(make_float2(o[0], o[1]));
    __nv_bfloat162 b1 = __float22bfloat162_rn(make_float2(o[2], o[3]));
    __nv_bfloat162 b2 = __float22bfloat162_rn(make_float2(o[4], o[5]));
    __nv_bfloat162 b3 = __float22bfloat162_rn(make_float2(o[6], o[7]));
    uint4 u;
    u.x = *reinterpret_cast<uint32_t*>(&b0);
    u.y = *reinterpret_cast<uint32_t*>(&b1);
    u.z = *reinterpret_cast<uint32_t*>(&b2);
    u.w = *reinterpret_cast<uint32_t*>(&b3);
    *reinterpret_cast<uint4*>(p) = u;
}
__device__ __forceinline__ float4 ld_bf16x4(const __nv_bfloat16* p) {
    uint2 raw = *reinterpret_cast<const uint2*>(p);
    __nv_bfloat162 p0 = *reinterpret_cast<__nv_bfloat162*>(&raw.x);
    __nv_bfloat162 p1 = *reinterpret_cast<__nv_bfloat162*>(&raw.y);
    float2 f0 = __bfloat1622float2(p0);
    float2 f1 = __bfloat1622float2(p1);
    return make_float4(f0.x, f0.y, f1.x, f1.y);
}

// ---------------- device scratch ----------------
__device__ __align__(16) float g_hu [(size_t)NU * HD];
__device__ __align__(16) float g_hi [(size_t)NI * HD];
__device__ __align__(16) __nv_bfloat16 g_hub[(size_t)NU * HD];  // bf16 shadow of hu
__device__ __align__(16) __nv_bfloat16 g_hib[(size_t)NI * HD];  // bf16 shadow of hi
__device__ __align__(16) float g_agg[(size_t)NN * HD];   // layer-1 [agg_item | agg_user]
__device__ __align__(16) float g_aggu2[(size_t)NU * HD]; // layer-2 user agg

__device__ __align__(16) int g_deg[NN];
__device__ __align__(16) int g_rowptr[NN + 1];
__device__ __align__(16) int g_fill[NN];
__device__ __align__(16) int g_bsums[128];
__device__ __align__(16) int g_esrc[2 * NE];

// ---------------- zero ----------------
__global__ void zero_kernel(float4* __restrict__ p, int n4) {
    int i = blockIdx.x * blockDim.x + threadIdx.x;
    if (i < n4) p[i] = make_float4(0.f, 0.f, 0.f, 0.f);
}

// ---------------- CSR: histogram over both relations (2 edges/thread) ----------------
__global__ void hist2_kernel(const int* __restrict__ ei_a, const int* __restrict__ ei_b,
                             int* __restrict__ deg)
{
    int t = blockIdx.x * blockDim.x + threadIdx.x;
    if (t < NE / 2) {
        int2 d = *reinterpret_cast<const int2*>(ei_a + NE + 2 * t);
        atomicAdd(&deg[d.x], 1);
        atomicAdd(&deg[d.y], 1);
    } else if (t < NE) {
        int2 d = *reinterpret_cast<const int2*>(ei_b + NE + 2 * (t - NE / 2));
        atomicAdd(&deg[NI + d.x], 1);
        atomicAdd(&deg[NI + d.y], 1);
    }
}

// ---------------- CSR: two-level scan ----------------
__global__ void __launch_bounds__(1024) scan1_kernel(
    const int* __restrict__ deg, int* __restrict__ rowptr, int* __restrict__ bsums, int n)
{
    __shared__ int ws[32];
    const int tid = threadIdx.x, lane = tid & 31, wid = tid >> 5;
    int i = blockIdx.x * 1024 + tid;
    int v = (i < n) ? deg[i] : 0;
    int x = v;
#pragma unroll
    for (int off = 1; off < 32; off <<= 1) {
        int y = __shfl_up_sync(0xffffffffu, x, off);
        if (lane >= off) x += y;
    }
    if (lane == 31) ws[wid] = x;
    __syncthreads();
    if (tid < 32) {
        int s = ws[tid];
#pragma unroll
        for (int off = 1; off < 32; off <<= 1) {
            int y = __shfl_up_sync(0xffffffffu, s, off);
            if (tid >= off) s += y;
        }
        ws[tid] = s;
    }
    __syncthreads();
    int prev = wid ? ws[wid - 1] : 0;
    if (i < n) rowptr[i] = prev + x - v;
    if (tid == 1023) bsums[blockIdx.x] = prev + x;
}

__global__ void __launch_bounds__(1024) scan2_kernel(int* __restrict__ data, int n) {
    __shared__ int ws[32];
    const int tid = threadIdx.x, lane = tid & 31, wid = tid >> 5;
    int v = (tid < n) ? data[tid] : 0;
    int x = v;
#pragma unroll
    for (int off = 1; off < 32; off <<= 1) {
        int y = __shfl_up_sync(0xffffffffu, x, off);
        if (lane >= off) x += y;
    }
    if (lane == 31) ws[wid] = x;
    __syncthreads();
    if (tid < 32) {
        int s = ws[tid];
#pragma unroll
        for (int off = 1; off < 32; off <<= 1) {
            int y = __shfl_up_sync(0xffffffffu, s, off);
            if (tid >= off) s += y;
        }
        ws[tid] = s;
    }
    __syncthreads();
    int prev = wid ? ws[wid - 1] : 0;
    if (tid < n) data[tid] = prev + x - v;
}

__global__ void scan3_kernel(int* __restrict__ rowptr, int* __restrict__ fill,
                             const int* __restrict__ bsums, int n, int total)
{
    int i = blockIdx.x * blockDim.x + threadIdx.x;
    if (i < n) {
        int v = rowptr[i] + bsums[i >> 10];
        rowptr[i] = v;
        fill[i] = v;
    }
    if (i == 0) rowptr[n] = total;
}

// ---------------- CSR: fill edge-source buckets (2 edges/thread) ----------------
__global__ void fill2_kernel(const int* __restrict__ ei_a, const int* __restrict__ ei_b,
                             int* __restrict__ cursor, int* __restrict__ esrc)
{
    int t = blockIdx.x * blockDim.x + threadIdx.x;
    if (t < NE / 2) {
        int e = 2 * t;
        int2 d = *reinterpret_cast<const int2*>(ei_a + NE + e);
        int2 s = *reinterpret_cast<const int2*>(ei_a + e);
        esrc[atomicAdd(&cursor[d.x], 1)] = s.x;
        esrc[atomicAdd(&cursor[d.y], 1)] = s.y;
    } else if (t < NE) {
        int e = 2 * (t - NE / 2);
        int2 d = *reinterpret_cast<const int2*>(ei_b + NE + e);
        int2 s = *reinterpret_cast<const int2*>(ei_b + e);
        esrc[atomicAdd(&cursor[NI + d.x], 1)] = s.x;
        esrc[atomicAdd(&cursor[NI + d.y], 1)] = s.y;
    }
}

// ---------------- gather mean from bf16 shadows: one warp per dst node ----------------
// lane covers bf16 elements [lane*4, lane*4+4); accumulate fp32; agg written fp32.
__global__ void __launch_bounds__(256) gather_mean_kernel(
    const __nv_bfloat16* __restrict__ srcA, const __nv_bfloat16* __restrict__ srcB,
    const int* __restrict__ rowptr, const int* __restrict__ esrc,
    float* __restrict__ agg, int n, int split)
{
    int node = (blockIdx.x * blockDim.x + threadIdx.x) >> 5;
    int lane = threadIdx.x & 31;
    if (node >= n) return;
    const __nv_bfloat16* src_feat = (node < split) ? srcA : srcB;
    int beg = __ldg(&rowptr[node]);
    int end = __ldg(&rowptr[node + 1]);
    float4 acc = make_float4(0.f, 0.f, 0.f, 0.f);
    int e = beg;
    for (; e + 8 <= end; e += 8) {
        int s[8];
#pragma unroll
        for (int q = 0; q < 8; q++) s[q] = __ldg(&esrc[e + q]);
        float4 v[8];
#pragma unroll
        for (int q = 0; q < 8; q++)
            v[q] = ld_bf16x4(src_feat + (size_t)s[q] * HD + lane * 4);
#pragma unroll
        for (int q = 0; q < 8; q++) {
            acc.x += v[q].x; acc.y += v[q].y; acc.z += v[q].z; acc.w += v[q].w;
        }
    }
    for (; e + 2 <= end; e += 2) {
        int s0 = __ldg(&esrc[e]);
        int s1 = __ldg(&esrc[e + 1]);
        float4 v0 = ld_bf16x4(src_feat + (size_t)s0 * HD + lane * 4);
        float4 v1 = ld_bf16x4(src_feat + (size_t)s1 * HD + lane * 4);
        acc.x += v0.x + v1.x; acc.y += v0.y + v1.y;
        acc.z += v0.z + v1.z; acc.w += v0.w + v1.w;
    }
    if (e < end) {
        int s = __ldg(&esrc[e]);
        float4 v = ld_bf16x4(src_feat + (size_t)s * HD + lane * 4);
        acc.x += v.x; acc.y += v.y; acc.z += v.z; acc.w += v.w;
    }
    float inv = 1.0f / fmaxf((float)(end - beg), 1.0f);
    acc.x *= inv; acc.y *= inv; acc.z *= inv; acc.w *= inv;
    reinterpret_cast<float4*>(agg + (size_t)node * HD)[lane] = acc;
}

// ---------------- fused SAGE combine (FFMA2), in-place; optional bf16 shadow write ----
// h[r] = relu( L2norm(agg[r] @ Wl + bl + h[r] @ Wr) ) + h[r]
__global__ void __launch_bounds__(128) combine_kernel(
    const float* __restrict__ agg, float* __restrict__ h,
    __nv_bfloat16* __restrict__ hb,
    const float* __restrict__ wl, const float* __restrict__ bl,
    const float* __restrict__ wr, int n)
{
    __shared__ __align__(16) float As[16 * 64];
    __shared__ __align__(16) float Xs[16 * 64];
    __shared__ __align__(16) float Wls[16 * 128];
    __shared__ __align__(16) float Wrs[16 * 128];

    const int tid  = threadIdx.x;
    const int tx   = tid & 15;
    const int ty   = tid >> 4;
    const int row0 = blockIdx.x * 64;

    u64 acc[8][4];
#pragma unroll
    for (int i = 0; i < 8; i++)
#pragma unroll
        for (int j = 0; j < 4; j++) acc[i][j] = 0ull;

    const int lrow  = tid >> 1;
    const int lhalf = tid & 1;
    const int grow  = min(row0 + lrow, n - 1);

    for (int kc = 0; kc < 8; kc++) {
        const int k0 = kc * 16;
        {
            const float4* sl = reinterpret_cast<const float4*>(wl + k0 * 128);
            const float4* sr = reinterpret_cast<const float4*>(wr + k0 * 128);
            float4* dl = reinterpret_cast<float4*>(Wls);
            float4* dr = reinterpret_cast<float4*>(Wrs);
#pragma unroll
            for (int i = 0; i < 4; i++) {
                dl[tid + i * 128] = sl[tid + i * 128];
                dr[tid + i * 128] = sr[tid + i * 128];
            }
        }
        {
            const float* ap = agg + (size_t)grow * HD + k0 + lhalf * 8;
            const float* xp = h   + (size_t)grow * HD + k0 + lhalf * 8;
            float4 a0 = *reinterpret_cast<const float4*>(ap);
            float4 a1 = *reinterpret_cast<const float4*>(ap + 4);
            float4 x0 = *reinterpret_cast<const float4*>(xp);
            float4 x1 = *reinterpret_cast<const float4*>(xp + 4);
            int kb = lhalf * 8;
            As[(kb + 0) * 64 + lrow] = a0.x;
            As[(kb + 1) * 64 + lrow] = a0.y;
            As[(kb + 2) * 64 + lrow] = a0.z;
            As[(kb + 3) * 64 + lrow] = a0.w;
            As[(kb + 4) * 64 + lrow] = a1.x;
            As[(kb + 5) * 64 + lrow] = a1.y;
            As[(kb + 6) * 64 + lrow] = a1.z;
            As[(kb + 7) * 64 + lrow] = a1.w;
            Xs[(kb + 0) * 64 + lrow] = x0.x;
            Xs[(kb + 1) * 64 + lrow] = x0.y;
            Xs[(kb + 2) * 64 + lrow] = x0.z;
            Xs[(kb + 3) * 64 + lrow] = x0.w;
            Xs[(kb + 4) * 64 + lrow] = x1.x;
            Xs[(kb + 5) * 64 + lrow] = x1.y;
            Xs[(kb + 6) * 64 + lrow] = x1.z;
            Xs[(kb + 7) * 64 + lrow] = x1.w;
        }
        __syncthreads();

#pragma unroll 2
        for (int k = 0; k < 16; k++) {
            float4 a0 = *reinterpret_cast<float4*>(&As[k * 64 + ty * 8]);
            float4 a1 = *reinterpret_cast<float4*>(&As[k * 64 + ty * 8 + 4]);
            float4 x0 = *reinterpret_cast<float4*>(&Xs[k * 64 + ty * 8]);
            float4 x1 = *reinterpret_cast<float4*>(&Xs[k * 64 + ty * 8 + 4]);
            ulonglong2 L0 = *reinterpret_cast<ulonglong2*>(&Wls[k * 128 + tx * 8]);
            ulonglong2 L1 = *reinterpret_cast<ulonglong2*>(&Wls[k * 128 + tx * 8 + 4]);
            ulonglong2 R0 = *reinterpret_cast<ulonglong2*>(&Wrs[k * 128 + tx * 8]);
            ulonglong2 R1 = *reinterpret_cast<ulonglong2*>(&Wrs[k * 128 + tx * 8 + 4]);
            u64 lv[4] = {L0.x, L0.y, L1.x, L1.y};
            u64 rv[4] = {R0.x, R0.y, R1.x, R1.y};
            float av[8] = {a0.x, a0.y, a0.z, a0.w, a1.x, a1.y, a1.z, a1.w};
            float xv[8] = {x0.x, x0.y, x0.z, x0.w, x1.x, x1.y, x1.z, x1.w};
#pragma unroll
            for (int i = 0; i < 8; i++) {
                u64 ap2 = pk2(av[i]);
                u64 xp2 = pk2(xv[i]);
#pragma unroll
                for (int j = 0; j < 4; j++) {
                    fma2(acc[i][j], ap2, lv[j]);
                    fma2(acc[i][j], xp2, rv[j]);
                }
            }
        }
        __syncthreads();
    }

    float bias[8];
#pragma unroll
    for (int j = 0; j < 8; j++) bias[j] = __ldg(&bl[tx * 8 + j]);

#pragma unroll
    for (int i = 0; i < 8; i++) {
        float v[8];
        float ss = 0.f;
#pragma unroll
        for (int j = 0; j < 4; j++) {
            float2 t = up2(acc[i][j]);
            v[2 * j]     = t.x + bias[2 * j];
            v[2 * j + 1] = t.y + bias[2 * j + 1];
            ss = fmaf(v[2 * j], v[2 * j], ss);
            ss = fmaf(v[2 * j + 1], v[2 * j + 1], ss);
        }
#pragma unroll
        for (int m = 8; m >= 1; m >>= 1)
            ss += __shfl_xor_sync(0xffffffffu, ss, m, 16);
        float inv = 1.0f / fmaxf(sqrtf(ss), 1e-12f);
        int gr = row0 + ty * 8 + i;
        if (gr < n) {
            float* hp = h + (size_t)gr * HD + tx * 8;
            float4 h0 = *reinterpret_cast<float4*>(hp);
            float4 h1 = *reinterpret_cast<float4*>(hp + 4);
            float o[8] = {h0.x, h0.y, h0.z, h0.w, h1.x, h1.y, h1.z, h1.w};
#pragma unroll
            for (int j = 0; j < 8; j++) o[j] += fmaxf(v[j] * inv, 0.0f);
            *reinterpret_cast<float4*>(hp)     = make_float4(o[0], o[1], o[2], o[3]);
            *reinterpret_cast<float4*>(hp + 4) = make_float4(o[4], o[5], o[6], o[7]);
            if (hb) store_bf16x8(hb + (size_t)gr * HD + tx * 8, o);
        }
    }
}

// ---------------- register-tiled dense + relu (FFMA2) — encoders; writes bf16 shadow ----
template<int K, int N>
__global__ void __launch_bounds__(128) mlp_relu_kernel(
    const float* __restrict__ x, const float* __restrict__ W,
    const float* __restrict__ b, float* __restrict__ out,
    __nv_bfloat16* __restrict__ out_b, int n)
{
    constexpr int TX = N / 8;
    constexpr int TY = 128 / TX;
    constexpr int BM = TY * 8;
    __shared__ __align__(16) float Xs[16 * BM];
    __shared__ __align__(16) float Ws[16 * N];

    const int tid  = threadIdx.x;
    const int tx   = tid % TX;
    const int ty   = tid / TX;
    const int row0 = blockIdx.x * BM;

    u64 acc[8][4];
#pragma unroll
    for (int i = 0; i < 8; i++)
#pragma unroll
        for (int j = 0; j < 4; j++) acc[i][j] = 0ull;

#pragma unroll 1
    for (int kc = 0; kc < K / 16; kc++) {
        const int k0 = kc * 16;
#pragma unroll
        for (int i = tid; i < 16 * N / 4; i += 128)
            reinterpret_cast<float4*>(Ws)[i] =
                reinterpret_cast<const float4*>(W + (size_t)k0 * N)[i];
#pragma unroll
        for (int idx = tid; idx < BM * 2; idx += 128) {
            int r = idx >> 1, half = idx & 1;
            int gr = min(row0 + r, n - 1);
            const float* xp = x + (size_t)gr * K + k0 + half * 8;
            float4 x0 = *reinterpret_cast<const float4*>(xp);
            float4 x1 = *reinterpret_cast<const float4*>(xp + 4);
            int kb = half * 8;
            Xs[(kb + 0) * BM + r] = x0.x;
            Xs[(kb + 1) * BM + r] = x0.y;
            Xs[(kb + 2) * BM + r] = x0.z;
            Xs[(kb + 3) * BM + r] = x0.w;
            Xs[(kb + 4) * BM + r] = x1.x;
            Xs[(kb + 5) * BM + r] = x1.y;
            Xs[(kb + 6) * BM + r] = x1.z;
            Xs[(kb + 7) * BM + r] = x1.w;
        }
        __syncthreads();

#pragma unroll 2
        for (int k = 0; k < 16; k++) {
            float4 a0 = *reinterpret_cast<float4*>(&Xs[k * BM + ty * 8]);
            float4 a1 = *reinterpret_cast<float4*>(&Xs[k * BM + ty * 8 + 4]);
            ulonglong2 W0 = *reinterpret_cast<ulonglong2*>(&Ws[k * N + tx * 8]);
            ulonglong2 W1 = *reinterpret_cast<ulonglong2*>(&Ws[k * N + tx * 8 + 4]);
            u64 wv[4] = {W0.x, W0.y, W1.x, W1.y};
            float av[8] = {a0.x, a0.y, a0.z, a0.w, a1.x, a1.y, a1.z, a1.w};
#pragma unroll
            for (int i = 0; i < 8; i++) {
                u64 ap2 = pk2(av[i]);
#pragma unroll
                for (int j = 0; j < 4; j++)
                    fma2(acc[i][j], ap2, wv[j]);
            }
        }
        __syncthreads();
    }

    float bias[8];
#pragma unroll
    for (int j = 0; j < 8; j++) bias[j] = __ldg(&b[tx * 8 + j]);

#pragma unroll
    for (int i = 0; i < 8; i++) {
        int gr = row0 + ty * 8 + i;
        if (gr < n) {
            float o[8];
#pragma unroll
            for (int j = 0; j < 4; j++) {
                float2 t = up2(acc[i][j]);
                o[2 * j]     = fmaxf(t.x + bias[2 * j], 0.0f);
                o[2 * j + 1] = fmaxf(t.y + bias[2 * j + 1], 0.0f);
            }
            float* op = out + (size_t)gr * N + tx * 8;
            *reinterpret_cast<float4*>(op)     = make_float4(o[0], o[1], o[2], o[3]);
            *reinterpret_cast<float4*>(op + 4) = make_float4(o[4], o[5], o[6], o[7]);
            if (out_b) store_bf16x8(out_b + (size_t)gr * N + tx * 8, o);
        }
    }
}

// ---------------- fused head: out = relu(hu @ w1 + b1) @ w2 + b2 ----------------
__global__ void __launch_bounds__(128) head_fused_kernel(
    const float* __restrict__ x, const float* __restrict__ w1,
    const float* __restrict__ b1, const float* __restrict__ w2,
    const float* __restrict__ b2, float* __restrict__ out, int n)
{
    constexpr int N = 64, TX = 8, BM = 128;
    __shared__ __align__(16) float Xs[16 * BM];
    __shared__ __align__(16) float Ws[16 * N];
    __shared__ __align__(16) float Zs[BM * N];
    __shared__ __align__(16) float W2s[64 * 8];

    const int tid  = threadIdx.x;
    const int tx   = tid % TX;
    const int ty   = tid / TX;
    const int row0 = blockIdx.x * BM;

#pragma unroll
    for (int i = tid; i < 64 * 8 / 4; i += 128)
        reinterpret_cast<float4*>(W2s)[i] = reinterpret_cast<const float4*>(w2)[i];

    u64 acc[8][4];
#pragma unroll
    for (int i = 0; i < 8; i++)
#pragma unroll
        for (int j = 0; j < 4; j++) acc[i][j] = 0ull;

#pragma unroll 1
    for (int kc = 0; kc < 8; kc++) {
        const int k0 = kc * 16;
#pragma unroll
        for (int i = tid; i < 16 * N / 4; i += 128)
            reinterpret_cast<float4*>(Ws)[i] =
                reinterpret_cast<const float4*>(w1 + (size_t)k0 * N)[i];
#pragma unroll
        for (int idx = tid; idx < BM * 2; idx += 128) {
            int r = idx >> 1, half = idx & 1;
            int gr = min(row0 + r, n - 1);
            const float* xp = x + (size_t)gr * HD + k0 + half * 8;
            float4 x0 = *reinterpret_cast<const float4*>(xp);
            float4 x1 = *reinterpret_cast<const float4*>(xp + 4);
            int kb = half * 8;
            Xs[(kb + 0) * BM + r] = x0.x;
            Xs[(kb + 1) * BM + r] = x0.y;
            Xs[(kb + 2) * BM + r] = x0.z;
            Xs[(kb + 3) * BM + r] = x0.w;
            Xs[(kb + 4) * BM + r] = x1.x;
            Xs[(kb + 5) * BM + r] = x1.y;
            Xs[(kb + 6) * BM + r] = x1.z;
            Xs[(kb + 7) * BM + r] = x1.w;
        }
        __syncthreads();

#pragma unroll 2
        for (int k = 0; k < 16; k++) {
            float4 a0 = *reinterpret_cast<float4*>(&Xs[k * BM + ty * 8]);
            float4 a1 = *reinterpret_cast<float4*>(&Xs[k * BM + ty * 8 + 4]);
            ulonglong2 W0 = *reinterpret_cast<ulonglong2*>(&Ws[k * N + tx * 8]);
            ulonglong2 W1 = *reinterpret_cast<ulonglong2*>(&Ws[k * N + tx * 8 + 4]);
            u64 wv[4] = {W0.x, W0.y, W1.x, W1.y};
            float av[8] = {a0.x, a0.y, a0.z, a0.w, a1.x, a1.y, a1.z, a1.w};
#pragma unroll
            for (int i = 0; i < 8; i++) {
                u64 ap2 = pk2(av[i]);
#pragma unroll
                for (int j = 0; j < 4; j++)
                    fma2(acc[i][j], ap2, wv[j]);
            }
        }
        __syncthreads();
    }

    float bias[8];
#pragma unroll
    for (int j = 0; j < 8; j++) bias[j] = __ldg(&b1[tx * 8 + j]);

#pragma unroll
    for (int i = 0; i < 8; i++) {
        int r = ty * 8 + i;
        float o[8];
#pragma unroll
        for (int j = 0; j < 4; j++) {
            float2 t = up2(acc[i][j]);
            o[2 * j]     = fmaxf(t.x + bias[2 * j], 0.0f);
            o[2 * j + 1] = fmaxf(t.y + bias[2 * j + 1], 0.0f);
        }
        float* zp = &Zs[r * N + tx * 8];
        *reinterpret_cast<float4*>(zp)     = make_float4(o[0], o[1], o[2], o[3]);
        *reinterpret_cast<float4*>(zp + 4) = make_float4(o[4], o[5], o[6], o[7]);
    }
    __syncthreads();

    int gr = row0 + tid;
    if (gr < n) {
        float a2[8];
#pragma unroll
        for (int j = 0; j < 8; j++) a2[j] = __ldg(&b2[j]);
        const float* zr = &Zs[tid * N];
#pragma unroll
        for (int k = 0; k < 64; k++) {
            float zv = zr[k];
#pragma unroll
            for (int j = 0; j < 8; j++)
                a2[j] = fmaf(zv, W2s[k * 8 + j], a2[j]);
        }
        float* op = out + (size_t)gr * 8;
        *reinterpret_cast<float4*>(op)     = make_float4(a2[0], a2[1], a2[2], a2[3]);
        *reinterpret_cast<float4*>(op + 4) = make_float4(a2[4], a2[5], a2[6], a2[7]);
    }
}

// ---------------- stream/event resources (created once at static init) ----------------
struct GraphRes {
    cudaStream_t s1;
    cudaEvent_t ev0, ev_enc, ev_fork, ev_cu1;
    GraphRes() {
        cudaStreamCreateWithFlags(&s1, cudaStreamNonBlocking);
        cudaEventCreateWithFlags(&ev0,    cudaEventDisableTiming);
        cudaEventCreateWithFlags(&ev_enc, cudaEventDisableTiming);
        cudaEventCreateWithFlags(&ev_fork, cudaEventDisableTiming);
        cudaEventCreateWithFlags(&ev_cu1, cudaEventDisableTiming);
    }
};
static GraphRes g_res;

// ---------------- launch ----------------
static float* sym_addr_f(const void* sym) {
    void* p = nullptr;
    cudaGetSymbolAddress(&p, sym);
    return reinterpret_cast<float*>(p);
}
static __nv_bfloat16* sym_addr_b(const void* sym) {
    void* p = nullptr;
    cudaGetSymbolAddress(&p, sym);
    return reinterpret_cast<__nv_bfloat16*>(p);
}
static int* sym_addr_i(const void* sym) {
    void* p = nullptr;
    cudaGetSymbolAddress(&p, sym);
    return reinterpret_cast<int*>(p);
}

extern "C" void kernel_launch(void* const* d_in, const int* in_sizes, int n_in,
                              void* d_out, int out_size)
{
    const float* x_user  = (const float*)d_in[0];
    const float* x_item  = (const float*)d_in[1];
    const int*   ei_u2i  = (const int*)d_in[2];
    const int*   ei_i2u  = (const int*)d_in[3];
    const float* enc_uw  = (const float*)d_in[4];
    const float* enc_ub  = (const float*)d_in[5];
    const float* enc_iw  = (const float*)d_in[6];
    const float* enc_ib  = (const float*)d_in[7];
    const float* L[12];
    for (int i = 0; i < 12; i++) L[i] = (const float*)d_in[8 + i];
    const float* head_w1 = (const float*)d_in[20];
    const float* head_b1 = (const float*)d_in[21];
    const float* head_w2 = (const float*)d_in[22];
    const float* head_b2 = (const float*)d_in[23];
    float* out = (float*)d_out;

    float* hu     = sym_addr_f(g_hu);
    float* hi     = sym_addr_f(g_hi);
    __nv_bfloat16* hub = sym_addr_b(g_hub);
    __nv_bfloat16* hib = sym_addr_b(g_hib);
    float* agg    = sym_addr_f(g_agg);
    float* agg_i  = agg;
    float* agg_u  = agg + (size_t)NI * HD;
    float* agg_u2 = sym_addr_f(g_aggu2);

    int* deg    = sym_addr_i(g_deg);
    int* rowptr = sym_addr_i(g_rowptr);
    int* fill   = sym_addr_i(g_fill);
    int* bsums  = sym_addr_i(g_bsums);
    int* esrc   = sym_addr_i(g_esrc);

    cudaStream_t s1 = g_res.s1;
    const int EBV = (NE + 255) / 256;
    const int NB1 = (NN + 1023) / 1024;

    // ---- fork: encoders on s1, CSR build on main ----
    cudaEventRecord(g_res.ev0, 0);
    cudaStreamWaitEvent(s1, g_res.ev0, 0);

    mlp_relu_kernel<64, 128><<<(NU + 63) / 64, 128, 0, s1>>>(x_user, enc_uw, enc_ub, hu, hub, NU);
    mlp_relu_kernel<32, 128><<<(NI + 63) / 64, 128, 0, s1>>>(x_item, enc_iw, enc_ib, hi, hib, NI);
    cudaEventRecord(g_res.ev_enc, s1);

    zero_kernel<<<(NN / 4 + 255) / 256, 256>>>((float4*)deg, NN / 4);
    hist2_kernel<<<EBV, 256>>>(ei_u2i, ei_i2u, deg);
    scan1_kernel<<<NB1, 1024>>>(deg, rowptr, bsums, NN);
    scan2_kernel<<<1, 1024>>>(bsums, NB1);
    scan3_kernel<<<(NN + 255) / 256, 256>>>(rowptr, fill, bsums, NN, 2 * NE);
    fill2_kernel<<<EBV, 256>>>(ei_u2i, ei_i2u, fill, esrc);

    // join: gathers need both encoders and CSR
    cudaStreamWaitEvent(0, g_res.ev_enc, 0);

    // ---- layer 1: both gathers in one launch (items read hub, users read hib) ----
    gather_mean_kernel<<<(NN * 32 + 255) / 256, 256>>>(hub, hib, rowptr, esrc, agg, NN, NI);

    // fork: c_u1 on s1 (reads agg_u + hu, in-place on hu; no shadow needed)
    cudaEventRecord(g_res.ev_fork, 0);
    cudaStreamWaitEvent(s1, g_res.ev_fork, 0);
    combine_kernel<<<(NU + 63) / 64, 128, 0, s1>>>(agg_u, hu, nullptr, L[3], L[4], L[5], NU);
    cudaEventRecord(g_res.ev_cu1, s1);

    // main: c_i1 (in-place on hi, refreshes hib shadow), then layer-2 user gather
    combine_kernel<<<(NI + 63) / 64, 128>>>(agg_i, hi, hib, L[0], L[1], L[2], NI);
    gather_mean_kernel<<<(NU * 32 + 255) / 256, 256>>>(hib, hib, rowptr + NI, esrc, agg_u2, NU, 0);

    // join: c_u2 needs agg_u2 (main) + updated hu (s1)
    cudaStreamWaitEvent(0, g_res.ev_cu1, 0);

    // ---- layer 2: only the user path feeds the head (item update is dead code) ----
    combine_kernel<<<(NU + 63) / 64, 128>>>(agg_u2, hu, nullptr, L[9], L[10], L[11], NU);

    // ---- fused head ----
    head_fused_kernel<<<(NU + 127) / 128, 128>>>(hu, head_w1, head_b1, head_w2, head_b2, out, NU);
}

// round 16
// speedup vs baseline: 1.7464x; 1.3401x over previous
#include <cuda_runtime.h>
#include <cuda_bf16.h>
#include <cstdint>

#define NU 50000
#define NI 50000
#define NE 800000
#define HD 128
#define NN (NI + NU)
#define NT2 782             // 64-row tiles covering 50048 rows
#define PADROWS (NT2 * 64)  // padded row count for agg buffers

typedef unsigned long long u64;

// ---------------- f32x2 packed-FMA helpers (Blackwell FFMA2) ----------------
__device__ __forceinline__ u64 pk2(float v) {
    u64 r; asm("mov.b64 %0, {%1,%1};" : "=l"(r) : "f"(v)); return r;
}
__device__ __forceinline__ void fma2(u64& d, u64 a, u64 b) {
    asm("fma.rn.f32x2 %0, %1, %2, %3;" : "=l"(d) : "l"(a), "l"(b), "l"(d));
}
__device__ __forceinline__ float2 up2(u64 v) {
    float2 f; asm("mov.b64 {%0,%1}, %2;" : "=f"(f.x), "=f"(f.y) : "l"(v)); return f;
}

// ---------------- bf16 pack/unpack helpers ----------------
__device__ __forceinline__ void store_bf16x8(__nv_bfloat16* p, const float* o) {
    __nv_bfloat162 b0 = __float22bfloat162_rn(make_float2(o[0], o[1]));
    __nv_bfloat162 b1 = __float22bfloat162_rn(make_float2(o[2], o[3]));
    __nv_bfloat162 b2 = __float22bfloat162_rn(make_float2(o[4], o[5]));
    __nv_bfloat162 b3 = __float22bfloat162_rn(make_float2(o[6], o[7]));
    uint4 u;
    u.x = *reinterpret_cast<uint32_t*>(&b0);
    u.y = *reinterpret_cast<uint32_t*>(&b1);
    u.z = *reinterpret_cast<uint32_t*>(&b2);
    u.w = *reinterpret_cast<uint32_t*>(&b3);
    *reinterpret_cast<uint4*>(p) = u;
}
__device__ __forceinline__ float4 ld_bf16x4(const __nv_bfloat16* p) {
    uint2 raw = *reinterpret_cast<const uint2*>(p);
    __nv_bfloat162 p0 = *reinterpret_cast<__nv_bfloat162*>(&raw.x);
    __nv_bfloat162 p1 = *reinterpret_cast<__nv_bfloat162*>(&raw.y);
    float2 f0 = __bfloat1622float2(p0);
    float2 f1 = __bfloat1622float2(p1);
    return make_float4(f0.x, f0.y, f1.x, f1.y);
}

// ---------------- device scratch ----------------
__device__ __align__(16) float g_hu [(size_t)NU * HD];
__device__ __align__(16) float g_hi [(size_t)NI * HD];
__device__ __align__(16) __nv_bfloat16 g_hub[(size_t)(NU + 128) * HD]; // padded shadows
__device__ __align__(16) __nv_bfloat16 g_hib[(size_t)(NI + 128) * HD];
__device__ __align__(16) __nv_bfloat16 g_agg_i [(size_t)PADROWS * HD]; // bf16 row-major means
__device__ __align__(16) __nv_bfloat16 g_agg_u [(size_t)PADROWS * HD];
__device__ __align__(16) __nv_bfloat16 g_agg_u2[(size_t)PADROWS * HD];
__device__ __align__(16) __nv_bfloat16 g_wT[6 * HD * HD];  // WT[n][k] bf16 per matrix

__device__ __align__(16) int g_deg[NN];
__device__ __align__(16) int g_rowptr[NN + 1];
__device__ __align__(16) int g_fill[NN];
__device__ __align__(16) int g_bsums[128];
__device__ __align__(16) int g_esrc[2 * NE];

// ---------------- zero ----------------
__global__ void zero_kernel(float4* __restrict__ p, int n4) {
    int i = blockIdx.x * blockDim.x + threadIdx.x;
    if (i < n4) p[i] = make_float4(0.f, 0.f, 0.f, 0.f);
}

// ---------------- weight prep: f32 W[k][n] -> bf16 WT[n][k] (6 matrices) ----------------
__global__ void prep_w6_kernel(const float* w0, const float* w1, const float* w2,
                               const float* w3, const float* w4, const float* w5,
                               __nv_bfloat16* __restrict__ dst)
{
    const float* ws[6] = {w0, w1, w2, w3, w4, w5};
    int m = blockIdx.y;
    int idx = blockIdx.x * blockDim.x + threadIdx.x;   // = k*128 + n
    if (idx >= HD * HD) return;
    int k = idx >> 7, nn = idx & 127;
    dst[(size_t)m * HD * HD + nn * HD + k] = __float2bfloat16(__ldg(&ws[m][idx]));
}

// ---------------- CSR: histogram over both relations (2 edges/thread) ----------------
__global__ void hist2_kernel(const int* __restrict__ ei_a, const int* __restrict__ ei_b,
                             int* __restrict__ deg)
{
    int t = blockIdx.x * blockDim.x + threadIdx.x;
    if (t < NE / 2) {
        int2 d = *reinterpret_cast<const int2*>(ei_a + NE + 2 * t);
        atomicAdd(&deg[d.x], 1);
        atomicAdd(&deg[d.y], 1);
    } else if (t < NE) {
        int2 d = *reinterpret_cast<const int2*>(ei_b + NE + 2 * (t - NE / 2));
        atomicAdd(&deg[NI + d.x], 1);
        atomicAdd(&deg[NI + d.y], 1);
    }
}

// ---------------- CSR: two-level scan ----------------
__global__ void __launch_bounds__(1024) scan1_kernel(
    const int* __restrict__ deg, int* __restrict__ rowptr, int* __restrict__ bsums, int n)
{
    __shared__ int ws[32];
    const int tid = threadIdx.x, lane = tid & 31, wid = tid >> 5;
    int i = blockIdx.x * 1024 + tid;
    int v = (i < n) ? deg[i] : 0;
    int x = v;
#pragma unroll
    for (int off = 1; off < 32; off <<= 1) {
        int y = __shfl_up_sync(0xffffffffu, x, off);
        if (lane >= off) x += y;
    }
    if (lane == 31) ws[wid] = x;
    __syncthreads();
    if (tid < 32) {
        int s = ws[tid];
#pragma unroll
        for (int off = 1; off < 32; off <<= 1) {
            int y = __shfl_up_sync(0xffffffffu, s, off);
            if (tid >= off) s += y;
        }
        ws[tid] = s;
    }
    __syncthreads();
    int prev = wid ? ws[wid - 1] : 0;
    if (i < n) rowptr[i] = prev + x - v;
    if (tid == 1023) bsums[blockIdx.x] = prev + x;
}

__global__ void __launch_bounds__(1024) scan2_kernel(int* __restrict__ data, int n) {
    __shared__ int ws[32];
    const int tid = threadIdx.x, lane = tid & 31, wid = tid >> 5;
    int v = (tid < n) ? data[tid] : 0;
    int x = v;
#pragma unroll
    for (int off = 1; off < 32; off <<= 1) {
        int y = __shfl_up_sync(0xffffffffu, x, off);
        if (lane >= off) x += y;
    }
    if (lane == 31) ws[wid] = x;
    __syncthreads();
    if (tid < 32) {
        int s = ws[tid];
#pragma unroll
        for (int off = 1; off < 32; off <<= 1) {
            int y = __shfl_up_sync(0xffffffffu, s, off);
            if (tid >= off) s += y;
        }
        ws[tid] = s;
    }
    __syncthreads();
    int prev = wid ? ws[wid - 1] : 0;
    if (tid < n) data[tid] = prev + x - v;
}

__global__ void scan3_kernel(int* __restrict__ rowptr, int* __restrict__ fill,
                             const int* __restrict__ bsums, int n, int total)
{
    int i = blockIdx.x * blockDim.x + threadIdx.x;
    if (i < n) {
        int v = rowptr[i] + bsums[i >> 10];
        rowptr[i] = v;
        fill[i] = v;
    }
    if (i == 0) rowptr[n] = total;
}

// ---------------- CSR: fill edge-source buckets (2 edges/thread) ----------------
__global__ void fill2_kernel(const int* __restrict__ ei_a, const int* __restrict__ ei_b,
                             int* __restrict__ cursor, int* __restrict__ esrc)
{
    int t = blockIdx.x * blockDim.x + threadIdx.x;
    if (t < NE / 2) {
        int e = 2 * t;
        int2 d = *reinterpret_cast<const int2*>(ei_a + NE + e);
        int2 s = *reinterpret_cast<const int2*>(ei_a + e);
        esrc[atomicAdd(&cursor[d.x], 1)] = s.x;
        esrc[atomicAdd(&cursor[d.y], 1)] = s.y;
    } else if (t < NE) {
        int e = 2 * (t - NE / 2);
        int2 d = *reinterpret_cast<const int2*>(ei_b + NE + e);
        int2 s = *reinterpret_cast<const int2*>(ei_b + e);
        esrc[atomicAdd(&cursor[NI + d.x], 1)] = s.x;
        esrc[atomicAdd(&cursor[NI + d.y], 1)] = s.y;
    }
}

// ---------------- gather mean -> bf16 row-major; one warp per dst node ----------------
__global__ void __launch_bounds__(256) gather_mean_kernel(
    const __nv_bfloat16* __restrict__ srcA, const __nv_bfloat16* __restrict__ srcB,
    const int* __restrict__ rowptr, const int* __restrict__ esrc,
    __nv_bfloat16* __restrict__ outA, __nv_bfloat16* __restrict__ outB,
    int n, int split)
{
    int node = (blockIdx.x * blockDim.x + threadIdx.x) >> 5;
    int lane = threadIdx.x & 31;
    if (node >= n) return;
    const __nv_bfloat16* src_feat;
    __nv_bfloat16* outp;
    int node2;
    if (node < split) { src_feat = srcA; outp = outA; node2 = node; }
    else              { src_feat = srcB; outp = outB; node2 = node - split; }

    int beg = __ldg(&rowptr[node]);
    int end = __ldg(&rowptr[node + 1]);
    float4 acc = make_float4(0.f, 0.f, 0.f, 0.f);
    int e = beg;
    for (; e + 8 <= end; e += 8) {
        int s[8];
#pragma unroll
        for (int q = 0; q < 8; q++) s[q] = __ldg(&esrc[e + q]);
        float4 v[8];
#pragma unroll
        for (int q = 0; q < 8; q++)
            v[q] = ld_bf16x4(src_feat + (size_t)s[q] * HD + lane * 4);
#pragma unroll
        for (int q = 0; q < 8; q++) {
            acc.x += v[q].x; acc.y += v[q].y; acc.z += v[q].z; acc.w += v[q].w;
        }
    }
    for (; e + 2 <= end; e += 2) {
        int s0 = __ldg(&esrc[e]);
        int s1 = __ldg(&esrc[e + 1]);
        float4 v0 = ld_bf16x4(src_feat + (size_t)s0 * HD + lane * 4);
        float4 v1 = ld_bf16x4(src_feat + (size_t)s1 * HD + lane * 4);
        acc.x += v0.x + v1.x; acc.y += v0.y + v1.y;
        acc.z += v0.z + v1.z; acc.w += v0.w + v1.w;
    }
    if (e < end) {
        int s = __ldg(&esrc[e]);
        float4 v = ld_bf16x4(src_feat + (size_t)s * HD + lane * 4);
        acc.x += v.x; acc.y += v.y; acc.z += v.z; acc.w += v.w;
    }
    float inv = 1.0f / fmaxf((float)(end - beg), 1.0f);
    acc.x *= inv; acc.y *= inv; acc.z *= inv; acc.w *= inv;

    __nv_bfloat162 b0 = __float22bfloat162_rn(make_float2(acc.x, acc.y));
    __nv_bfloat162 b1 = __float22bfloat162_rn(make_float2(acc.z, acc.w));
    uint2 u = make_uint2(*reinterpret_cast<uint32_t*>(&b0), *reinterpret_cast<uint32_t*>(&b1));
    *reinterpret_cast<uint2*>(outp + (size_t)node2 * HD + lane * 4) = u;
}

// ---------------- HMMA combine: 64 rows/block, 128 threads (4 warps, 16 rows each) ---
// h[r] = relu( L2norm( agg[r]@Wl + bl + h[r]@Wr ) ) + h[r]
// mma.sync m16n8k16 bf16->f32. Plain LDS fragment loads per PTX ISA thread mapping.
#define WSTR 136   // padded smem row stride (bf16); 136*2B=272B ≡ 4 words mod 32 -> conflict-free
static constexpr int CMB_SMEM = 512 + 2 * (128 * WSTR * 2) + 2 * (64 * WSTR * 2); // 104960

__global__ void __launch_bounds__(128) combine_mma_kernel(
    const __nv_bfloat16* __restrict__ aggB,   // bf16 row-major [PADROWS][128]
    const __nv_bfloat16* __restrict__ hb_in,  // bf16 row-major padded
    float* __restrict__ h_io,
    __nv_bfloat16* __restrict__ hb_out,       // nullable shadow refresh
    const __nv_bfloat16* __restrict__ wlT,    // WT[n][k] 128x128 bf16
    const __nv_bfloat16* __restrict__ wrT,
    const float* __restrict__ bl, int n)
{
    extern __shared__ __align__(16) char smem[];
    float* Bs = reinterpret_cast<float*>(smem);
    __nv_bfloat16* Wls = reinterpret_cast<__nv_bfloat16*>(smem + 512);
    __nv_bfloat16* Wrs = Wls + 128 * WSTR;
    __nv_bfloat16* Aas = Wrs + 128 * WSTR;
    __nv_bfloat16* Ahs = Aas + 64 * WSTR;

    const int tid  = threadIdx.x;
    const int w    = tid >> 5;
    const int lane = tid & 31;
    const int row0 = blockIdx.x * 64;

    Bs[tid] = __ldg(&bl[tid]);
    // stage weights (128x128 bf16 each) into padded smem
    for (int i = tid; i < 2048; i += 128) {
        int r = i >> 4, c = (i & 15) * 8;
        *reinterpret_cast<uint4*>(&Wls[r * WSTR + c]) =
            *reinterpret_cast<const uint4*>(&wlT[r * HD + c]);
        *reinterpret_cast<uint4*>(&Wrs[r * WSTR + c]) =
            *reinterpret_cast<const uint4*>(&wrT[r * HD + c]);
    }
    // stage A tiles (64x128 bf16 each)
    for (int i = tid; i < 1024; i += 128) {
        int r = i >> 4, c = (i & 15) * 8;
        *reinterpret_cast<uint4*>(&Aas[r * WSTR + c]) =
            *reinterpret_cast<const uint4*>(&aggB[(size_t)(row0 + r) * HD + c]);
        *reinterpret_cast<uint4*>(&Ahs[r * WSTR + c]) =
            *reinterpret_cast<const uint4*>(&hb_in[(size_t)(row0 + r) * HD + c]);
    }
    __syncthreads();

    float acc[16][4];
#pragma unroll
    for (int nt = 0; nt < 16; nt++)
#pragma unroll
        for (int j = 0; j < 4; j++) acc[nt][j] = 0.f;

    const int g  = lane >> 2;      // groupID 0..7
    const int tg = lane & 3;       // thread-in-group 0..3
    const int arow = w * 16 + g;   // fragment base row in tile

    const __nv_bfloat16* Ab[2] = {Aas, Ahs};
    const __nv_bfloat16* Wb[2] = {Wls, Wrs};
#pragma unroll
    for (int op = 0; op < 2; op++) {
        const __nv_bfloat16* A = Ab[op];
        const __nv_bfloat16* W = Wb[op];
#pragma unroll
        for (int ks = 0; ks < 8; ks++) {
            const int k0 = ks * 16;
            uint32_t a0 = *reinterpret_cast<const uint32_t*>(&A[(arow    ) * WSTR + k0 + tg * 2]);
            uint32_t a1 = *reinterpret_cast<const uint32_t*>(&A[(arow + 8) * WSTR + k0 + tg * 2]);
            uint32_t a2 = *reinterpret_cast<const uint32_t*>(&A[(arow    ) * WSTR + k0 + 8 + tg * 2]);
            uint32_t a3 = *reinterpret_cast<const uint32_t*>(&A[(arow + 8) * WSTR + k0 + 8 + tg * 2]);
#pragma unroll
            for (int nt = 0; nt < 16; nt++) {
                const int nn = nt * 8 + g;
                uint32_t b0 = *reinterpret_cast<const uint32_t*>(&W[nn * WSTR + k0 + tg * 2]);
                uint32_t b1 = *reinterpret_cast<const uint32_t*>(&W[nn * WSTR + k0 + 8 + tg * 2]);
                asm volatile(
                    "mma.sync.aligned.m16n8k16.row.col.f32.bf16.bf16.f32 "
                    "{%0,%1,%2,%3}, {%4,%5,%6,%7}, {%8,%9}, {%0,%1,%2,%3};"
                    : "+f"(acc[nt][0]), "+f"(acc[nt][1]), "+f"(acc[nt][2]), "+f"(acc[nt][3])
                    : "r"(a0), "r"(a1), "r"(a2), "r"(a3), "r"(b0), "r"(b1));
            }
        }
    }

    // epilogue: +bias, L2-norm per row (4 lanes/row), relu, fp32 residual, shadow refresh
    // thread owns rows r0 = row0 + w*16 + g and r1 = r0 + 8; cols nt*8 + tg*2 + {0,1}
    float v0[16][2], v1[16][2];
    float ss0 = 0.f, ss1 = 0.f;
#pragma unroll
    for (int nt = 0; nt < 16; nt++) {
        int c = nt * 8 + tg * 2;
        float b0f = Bs[c], b1f = Bs[c + 1];
        v0[nt][0] = acc[nt][0] + b0f;  v0[nt][1] = acc[nt][1] + b1f;
        v1[nt][0] = acc[nt][2] + b0f;  v1[nt][1] = acc[nt][3] + b1f;
        ss0 = fmaf(v0[nt][0], v0[nt][0], ss0); ss0 = fmaf(v0[nt][1], v0[nt][1], ss0);
        ss1 = fmaf(v1[nt][0], v1[nt][0], ss1); ss1 = fmaf(v1[nt][1], v1[nt][1], ss1);
    }
    ss0 += __shfl_xor_sync(0xffffffffu, ss0, 1);
    ss0 += __shfl_xor_sync(0xffffffffu, ss0, 2);
    ss1 += __shfl_xor_sync(0xffffffffu, ss1, 1);
    ss1 += __shfl_xor_sync(0xffffffffu, ss1, 2);
    float inv0 = 1.0f / fmaxf(sqrtf(ss0), 1e-12f);
    float inv1 = 1.0f / fmaxf(sqrtf(ss1), 1e-12f);

    const int r0 = row0 + w * 16 + g;
    const int r1 = r0 + 8;
#pragma unroll
    for (int half = 0; half < 2; half++) {
        int gr = half ? r1 : r0;
        float inv = half ? inv1 : inv0;
        float (*vv)[2] = half ? v1 : v0;
        if (gr < n) {
            float* hp = h_io + (size_t)gr * HD;
            __nv_bfloat16* hbp = hb_out ? (hb_out + (size_t)gr * HD) : nullptr;
#pragma unroll
            for (int nt = 0; nt < 16; nt++) {
                int c = nt * 8 + tg * 2;
                float2 h2 = *reinterpret_cast<const float2*>(hp + c);
                float o0 = h2.x + fmaxf(vv[nt][0] * inv, 0.0f);
                float o1 = h2.y + fmaxf(vv[nt][1] * inv, 0.0f);
                *reinterpret_cast<float2*>(hp + c) = make_float2(o0, o1);
                if (hbp) {
                    __nv_bfloat162 bb = __float22bfloat162_rn(make_float2(o0, o1));
                    *reinterpret_cast<uint32_t*>(hbp + c) = *reinterpret_cast<uint32_t*>(&bb);
                }
            }
        }
    }
}

// ---------------- register-tiled dense + relu (FFMA2) — encoders; writes bf16 shadow ----
template<int K, int N>
__global__ void __launch_bounds__(128) mlp_relu_kernel(
    const float* __restrict__ x, const float* __restrict__ W,
    const float* __restrict__ b, float* __restrict__ out,
    __nv_bfloat16* __restrict__ out_b, int n)
{
    constexpr int TX = N / 8;
    constexpr int TY = 128 / TX;
    constexpr int BM = TY * 8;
    __shared__ __align__(16) float Xs[16 * BM];
    __shared__ __align__(16) float Ws[16 * N];

    const int tid  = threadIdx.x;
    const int tx   = tid % TX;
    const int ty   = tid / TX;
    const int row0 = blockIdx.x * BM;

    u64 acc[8][4];
#pragma unroll
    for (int i = 0; i < 8; i++)
#pragma unroll
        for (int j = 0; j < 4; j++) acc[i][j] = 0ull;

#pragma unroll 1
    for (int kc = 0; kc < K / 16; kc++) {
        const int k0 = kc * 16;
#pragma unroll
        for (int i = tid; i < 16 * N / 4; i += 128)
            reinterpret_cast<float4*>(Ws)[i] =
                reinterpret_cast<const float4*>(W + (size_t)k0 * N)[i];
#pragma unroll
        for (int idx = tid; idx < BM * 2; idx += 128) {
            int r = idx >> 1, half = idx & 1;
            int gr = min(row0 + r, n - 1);
            const float* xp = x + (size_t)gr * K + k0 + half * 8;
            float4 x0 = *reinterpret_cast<const float4*>(xp);
            float4 x1 = *reinterpret_cast<const float4*>(xp + 4);
            int kb = half * 8;
            Xs[(kb + 0) * BM + r] = x0.x;
            Xs[(kb + 1) * BM + r] = x0.y;
            Xs[(kb + 2) * BM + r] = x0.z;
            Xs[(kb + 3) * BM + r] = x0.w;
            Xs[(kb + 4) * BM + r] = x1.x;
            Xs[(kb + 5) * BM + r] = x1.y;
            Xs[(kb + 6) * BM + r] = x1.z;
            Xs[(kb + 7) * BM + r] = x1.w;
        }
        __syncthreads();

#pragma unroll 2
        for (int k = 0; k < 16; k++) {
            float4 a0 = *reinterpret_cast<float4*>(&Xs[k * BM + ty * 8]);
            float4 a1 = *reinterpret_cast<float4*>(&Xs[k * BM + ty * 8 + 4]);
            ulonglong2 W0 = *reinterpret_cast<ulonglong2*>(&Ws[k * N + tx * 8]);
            ulonglong2 W1 = *reinterpret_cast<ulonglong2*>(&Ws[k * N + tx * 8 + 4]);
            u64 wv[4] = {W0.x, W0.y, W1.x, W1.y};
            float av[8] = {a0.x, a0.y, a0.z, a0.w, a1.x, a1.y, a1.z, a1.w};
#pragma unroll
            for (int i = 0; i < 8; i++) {
                u64 ap2 = pk2(av[i]);
#pragma unroll
                for (int j = 0; j < 4; j++)
                    fma2(acc[i][j], ap2, wv[j]);
            }
        }
        __syncthreads();
    }

    float bias[8];
#pragma unroll
    for (int j = 0; j < 8; j++) bias[j] = __ldg(&b[tx * 8 + j]);

#pragma unroll
    for (int i = 0; i < 8; i++) {
        int gr = row0 + ty * 8 + i;
        if (gr < n) {
            float o[8];
#pragma unroll
            for (int j = 0; j < 4; j++) {
                float2 t = up2(acc[i][j]);
                o[2 * j]     = fmaxf(t.x + bias[2 * j], 0.0f);
                o[2 * j + 1] = fmaxf(t.y + bias[2 * j + 1], 0.0f);
            }
            float* op = out + (size_t)gr * N + tx * 8;
            *reinterpret_cast<float4*>(op)     = make_float4(o[0], o[1], o[2], o[3]);
            *reinterpret_cast<float4*>(op + 4) = make_float4(o[4], o[5], o[6], o[7]);
            if (out_b) store_bf16x8(out_b + (size_t)gr * N + tx * 8, o);
        }
    }
}

// ---------------- fused head: out = relu(hu @ w1 + b1) @ w2 + b2 ----------------
__global__ void __launch_bounds__(128) head_fused_kernel(
    const float* __restrict__ x, const float* __restrict__ w1,
    const float* __restrict__ b1, const float* __restrict__ w2,
    const float* __restrict__ b2, float* __restrict__ out, int n)
{
    constexpr int N = 64, TX = 8, BM = 128;
    __shared__ __align__(16) float Xs[16 * BM];
    __shared__ __align__(16) float Ws[16 * N];
    __shared__ __align__(16) float Zs[BM * N];
    __shared__ __align__(16) float W2s[64 * 8];

    const int tid  = threadIdx.x;
    const int tx   = tid % TX;
    const int ty   = tid / TX;
    const int row0 = blockIdx.x * BM;

#pragma unroll
    for (int i = tid; i < 64 * 8 / 4; i += 128)
        reinterpret_cast<float4*>(W2s)[i] = reinterpret_cast<const float4*>(w2)[i];

    u64 acc[8][4];
#pragma unroll
    for (int i = 0; i < 8; i++)
#pragma unroll
        for (int j = 0; j < 4; j++) acc[i][j] = 0ull;

#pragma unroll 1
    for (int kc = 0; kc < 8; kc++) {
        const int k0 = kc * 16;
#pragma unroll
        for (int i = tid; i < 16 * N / 4; i += 128)
            reinterpret_cast<float4*>(Ws)[i] =
                reinterpret_cast<const float4*>(w1 + (size_t)k0 * N)[i];
#pragma unroll
        for (int idx = tid; idx < BM * 2; idx += 128) {
            int r = idx >> 1, half = idx & 1;
            int gr = min(row0 + r, n - 1);
            const float* xp = x + (size_t)gr * HD + k0 + half * 8;
            float4 x0 = *reinterpret_cast<const float4*>(xp);
            float4 x1 = *reinterpret_cast<const float4*>(xp + 4);
            int kb = half * 8;
            Xs[(kb + 0) * BM + r] = x0.x;
            Xs[(kb + 1) * BM + r] = x0.y;
            Xs[(kb + 2) * BM + r] = x0.z;
            Xs[(kb + 3) * BM + r] = x0.w;
            Xs[(kb + 4) * BM + r] = x1.x;
            Xs[(kb + 5) * BM + r] = x1.y;
            Xs[(kb + 6) * BM + r] = x1.z;
            Xs[(kb + 7) * BM + r] = x1.w;
        }
        __syncthreads();

#pragma unroll 2
        for (int k = 0; k < 16; k++) {
            float4 a0 = *reinterpret_cast<float4*>(&Xs[k * BM + ty * 8]);
            float4 a1 = *reinterpret_cast<float4*>(&Xs[k * BM + ty * 8 + 4]);
            ulonglong2 W0 = *reinterpret_cast<ulonglong2*>(&Ws[k * N + tx * 8]);
            ulonglong2 W1 = *reinterpret_cast<ulonglong2*>(&Ws[k * N + tx * 8 + 4]);
            u64 wv[4] = {W0.x, W0.y, W1.x, W1.y};
            float av[8] = {a0.x, a0.y, a0.z, a0.w, a1.x, a1.y, a1.z, a1.w};
#pragma unroll
            for (int i = 0; i < 8; i++) {
                u64 ap2 = pk2(av[i]);
#pragma unroll
                for (int j = 0; j < 4; j++)
                    fma2(acc[i][j], ap2, wv[j]);
            }
        }
        __syncthreads();
    }

    float bias[8];
#pragma unroll
    for (int j = 0; j < 8; j++) bias[j] = __ldg(&b1[tx * 8 + j]);

#pragma unroll
    for (int i = 0; i < 8; i++) {
        int r = ty * 8 + i;
        float o[8];
#pragma unroll
        for (int j = 0; j < 4; j++) {
            float2 t = up2(acc[i][j]);
            o[2 * j]     = fmaxf(t.x + bias[2 * j], 0.0f);
            o[2 * j + 1] = fmaxf(t.y + bias[2 * j + 1], 0.0f);
        }
        float* zp = &Zs[r * N + tx * 8];
        *reinterpret_cast<float4*>(zp)     = make_float4(o[0], o[1], o[2], o[3]);
        *reinterpret_cast<float4*>(zp + 4) = make_float4(o[4], o[5], o[6], o[7]);
    }
    __syncthreads();

    int gr = row0 + tid;
    if (gr < n) {
        float a2[8];
#pragma unroll
        for (int j = 0; j < 8; j++) a2[j] = __ldg(&b2[j]);
        const float* zr = &Zs[tid * N];
#pragma unroll
        for (int k = 0; k < 64; k++) {
            float zv = zr[k];
#pragma unroll
            for (int j = 0; j < 8; j++)
                a2[j] = fmaf(zv, W2s[k * 8 + j], a2[j]);
        }
        float* op = out + (size_t)gr * 8;
        *reinterpret_cast<float4*>(op)     = make_float4(a2[0], a2[1], a2[2], a2[3]);
        *reinterpret_cast<float4*>(op + 4) = make_float4(a2[4], a2[5], a2[6], a2[7]);
    }
}

// ---------------- stream/event resources ----------------
struct GraphRes {
    cudaStream_t s1;
    cudaEvent_t ev0, ev_enc, ev_fork, ev_cu1;
    GraphRes() {
        cudaStreamCreateWithFlags(&s1, cudaStreamNonBlocking);
        cudaEventCreateWithFlags(&ev0,    cudaEventDisableTiming);
        cudaEventCreateWithFlags(&ev_enc, cudaEventDisableTiming);
        cudaEventCreateWithFlags(&ev_fork, cudaEventDisableTiming);
        cudaEventCreateWithFlags(&ev_cu1, cudaEventDisableTiming);
    }
};
static GraphRes g_res;

// ---------------- launch ----------------
static float* sym_addr_f(const void* sym) {
    void* p = nullptr; cudaGetSymbolAddress(&p, sym); return (float*)p;
}
static __nv_bfloat16* sym_addr_b(const void* sym) {
    void* p = nullptr; cudaGetSymbolAddress(&p, sym); return (__nv_bfloat16*)p;
}
static int* sym_addr_i(const void* sym) {
    void* p = nullptr; cudaGetSymbolAddress(&p, sym); return (int*)p;
}

extern "C" void kernel_launch(void* const* d_in, const int* in_sizes, int n_in,
                              void* d_out, int out_size)
{
    const float* x_user  = (const float*)d_in[0];
    const float* x_item  = (const float*)d_in[1];
    const int*   ei_u2i  = (const int*)d_in[2];
    const int*   ei_i2u  = (const int*)d_in[3];
    const float* enc_uw  = (const float*)d_in[4];
    const float* enc_ub  = (const float*)d_in[5];
    const float* enc_iw  = (const float*)d_in[6];
    const float* enc_ib  = (const float*)d_in[7];
    const float* L[12];
    for (int i = 0; i < 12; i++) L[i] = (const float*)d_in[8 + i];
    const float* head_w1 = (const float*)d_in[20];
    const float* head_b1 = (const float*)d_in[21];
    const float* head_w2 = (const float*)d_in[22];
    const float* head_b2 = (const float*)d_in[23];
    float* out = (float*)d_out;

    float* hu = sym_addr_f(g_hu);
    float* hi = sym_addr_f(g_hi);
    __nv_bfloat16* hub = sym_addr_b(g_hub);
    __nv_bfloat16* hib = sym_addr_b(g_hib);
    __nv_bfloat16* agg_i  = sym_addr_b(g_agg_i);
    __nv_bfloat16* agg_u  = sym_addr_b(g_agg_u);
    __nv_bfloat16* agg_u2 = sym_addr_b(g_agg_u2);
    __nv_bfloat16* wT = sym_addr_b(g_wT);

    int* deg    = sym_addr_i(g_deg);
    int* rowptr = sym_addr_i(g_rowptr);
    int* fill   = sym_addr_i(g_fill);
    int* bsums  = sym_addr_i(g_bsums);
    int* esrc   = sym_addr_i(g_esrc);

    cudaFuncSetAttribute(combine_mma_kernel,
                         cudaFuncAttributeMaxDynamicSharedMemorySize, CMB_SMEM);

    cudaStream_t s1 = g_res.s1;
    const int EBV = (NE + 255) / 256;
    const int NB1 = (NN + 1023) / 1024;
    const size_t WSZ = (size_t)HD * HD;

    // ---- fork: encoders on s1, weight-prep + CSR build on main ----
    cudaEventRecord(g_res.ev0, 0);
    cudaStreamWaitEvent(s1, g_res.ev0, 0);

    mlp_relu_kernel<64, 128><<<(NU + 63) / 64, 128, 0, s1>>>(x_user, enc_uw, enc_ub, hu, hub, NU);
    mlp_relu_kernel<32, 128><<<(NI + 63) / 64, 128, 0, s1>>>(x_item, enc_iw, enc_ib, hi, hib, NI);
    cudaEventRecord(g_res.ev_enc, s1);

    // weight prep: {Wl_i1, Wr_i1, Wl_u1, Wr_u1, Wl_u2, Wr_u2} -> WT[n][k] bf16
    {
        dim3 grid((HD * HD + 255) / 256, 6);
        prep_w6_kernel<<<grid, 256>>>(L[0], L[2], L[3], L[5], L[9], L[11], wT);
    }
    zero_kernel<<<(NN / 4 + 255) / 256, 256>>>((float4*)deg, NN / 4);
    hist2_kernel<<<EBV, 256>>>(ei_u2i, ei_i2u, deg);
    scan1_kernel<<<NB1, 1024>>>(deg, rowptr, bsums, NN);
    scan2_kernel<<<1, 1024>>>(bsums, NB1);
    scan3_kernel<<<(NN + 255) / 256, 256>>>(rowptr, fill, bsums, NN, 2 * NE);
    fill2_kernel<<<EBV, 256>>>(ei_u2i, ei_i2u, fill, esrc);

    // join: gathers need encoders (shadows) and CSR
    cudaStreamWaitEvent(0, g_res.ev_enc, 0);

    // ---- layer 1: both gathers in one launch (items read hub, users read hib) ----
    gather_mean_kernel<<<(NN * 32 + 255) / 256, 256>>>(
        hub, hib, rowptr, esrc, agg_i, agg_u, NN, NI);

    // fork: c_u1 on s1 (reads agg_u + hub + hu; in-place hu; refreshes hub)
    cudaEventRecord(g_res.ev_fork, 0);
    cudaStreamWaitEvent(s1, g_res.ev_fork, 0);
    combine_mma_kernel<<<NT2, 128, CMB_SMEM, s1>>>(
        agg_u, hub, hu, hub, wT + 2 * WSZ, wT + 3 * WSZ, L[4], NU);
    cudaEventRecord(g_res.ev_cu1, s1);

    // main: c_i1 (in-place hi, refreshes hib), then layer-2 user gather (reads hib)
    combine_mma_kernel<<<NT2, 128, CMB_SMEM>>>(
        agg_i, hib, hi, hib, wT, wT + WSZ, L[1], NI);
    gather_mean_kernel<<<(NU * 32 + 255) / 256, 256>>>(
        hib, hib, rowptr + NI, esrc, agg_u2, agg_u2, NU, 0);

    // join: c_u2 needs agg_u2 (main) + updated hu/hub (s1)
    cudaStreamWaitEvent(0, g_res.ev_cu1, 0);

    // ---- layer 2: only the user path feeds the head ----
    combine_mma_kernel<<<NT2, 128, CMB_SMEM>>>(
        agg_u2, hub, hu, nullptr, wT + 4 * WSZ, wT + 5 * WSZ, L[10], NU);

    // ---- fused head (fp32) ----
    head_fused_kernel<<<(NU + 127) / 128, 128>>>(hu, head_w1, head_b1, head_w2, head_b2, out, NU);
}